// round 9
// baseline (speedup 1.0000x reference)
#include <cuda_runtime.h>
#include <cuda_fp16.h>
#include <cstdint>
#include <cstdio>

typedef unsigned short ushort_t;

// Problem constants
#define B_    8
#define N_TOK 1024
#define M_TOK 1024
#define E_    768
#define L_    768
#define H_    12
#define HD_   64
#define LN_EPS 1e-5f

// ---------------- scratch (static __device__ — no allocations allowed) -----
__device__ float    g_xn [B_ * N_TOK * E_];                     // fp32 (residual)
__device__ float    g_hn [B_ * N_TOK * E_];                     // fp32 (residual)
__device__ float    g_A  [(size_t)B_ * H_ * N_TOK * M_TOK];     // fp16 logits / fp32 hpre
__device__ uint32_t g_Ab [(size_t)B_ * H_ * N_TOK * M_TOK / 2]; // fp16 probs
__device__ uint32_t g_xyb[2 * B_ * N_TOK * E_ / 2];             // fp16 xn | yn
__device__ uint32_t g_hnb[B_ * N_TOK * E_ / 2];                 // fp16 hn
__device__ uint32_t g_qkb[2 * B_ * N_TOK * L_ / 2];             // fp16 q | k (q half reused: mid)
__device__ uint32_t g_Cb [(size_t)B_ * N_TOK * H_ * E_ / 2];    // C fp16
__device__ uint32_t g_ynT[B_ * E_ * M_TOK / 2];                 // ynT fp16
__device__ uint32_t g_wqkT[2 * L_ * E_ / 2];                    // wqT | wkT
__device__ uint32_t g_winT[L_ * E_ / 2];
__device__ uint32_t g_woutT[E_ * L_ / 2];
__device__ uint32_t g_w2T [E_ * H_ * E_ / 2];
__device__ float    g_bqk[2 * L_];                              // bq | bk
__device__ float    g_bsum[E_];

// ---------------- fp16 helpers ---------------------------------------------
__device__ __forceinline__ uint32_t hf2(float lo, float hi) {
    uint32_t r;
    asm("cvt.rn.f16x2.f32 %0, %1, %2;" : "=r"(r) : "f"(hi), "f"(lo));
    return r;
}
__device__ __forceinline__ ushort_t hf1(float f) {
    ushort_t h; asm("cvt.rn.f16.f32 %0, %1;" : "=h"(h) : "f"(f)); return h;
}
__device__ __forceinline__ void mma_f16(float& c0, float& c1, float& c2, float& c3,
                                        uint32_t a0, uint32_t a1, uint32_t a2, uint32_t a3,
                                        uint32_t b0, uint32_t b1) {
    asm volatile(
        "mma.sync.aligned.m16n8k16.row.col.f32.f16.f16.f32 "
        "{%0,%1,%2,%3}, {%4,%5,%6,%7}, {%8,%9}, {%0,%1,%2,%3};"
        : "+f"(c0), "+f"(c1), "+f"(c2), "+f"(c3)
        : "r"(a0), "r"(a1), "r"(a2), "r"(a3), "r"(b0), "r"(b1));
}
#define LDMX4(rg, addr) \
    asm volatile("ldmatrix.sync.aligned.m8n8.x4.shared.b16 {%0,%1,%2,%3}, [%4];" \
        : "=r"((rg)[0]), "=r"((rg)[1]), "=r"((rg)[2]), "=r"((rg)[3]) : "r"(addr))

// FMA-pipe exp
__device__ __forceinline__ float exp_fma(float d) {
    float z = fmaxf(d * 1.44269504f, -125.0f);
    float y = z + 12582912.0f;
    float r = y - 12582912.0f;
    float f = z - r;
    float p = 1.33335581e-3f;
    p = p * f + 9.61812910e-3f;
    p = p * f + 5.55041087e-2f;
    p = p * f + 2.40226507e-1f;
    p = p * f + 6.93147180e-1f;
    p = p * f + 1.0f;
    int iy = __float_as_int(y);
    return __int_as_float(__float_as_int(p) + (iy << 23));
}

// ---------------- LayerNorm core -------------------------------------------
__device__ __forceinline__ void ln_row(const float* __restrict__ x,
                                       const float* __restrict__ g,
                                       const float* __restrict__ b,
                                       float* __restrict__ outf,
                                       ushort_t* __restrict__ outh,
                                       float* red, int t) {
    float v[3];
    float s = 0.f;
#pragma unroll
    for (int i = 0; i < 3; i++) { v[i] = x[t + i * 256]; s += v[i]; }
    red[t] = s; __syncthreads();
    for (int st = 128; st > 0; st >>= 1) { if (t < st) red[t] += red[t + st]; __syncthreads(); }
    float mean = red[0] * (1.0f / E_); __syncthreads();

    float sq = 0.f;
#pragma unroll
    for (int i = 0; i < 3; i++) { float d = v[i] - mean; sq += d * d; }
    red[t] = sq; __syncthreads();
    for (int st = 128; st > 0; st >>= 1) { if (t < st) red[t] += red[t + st]; __syncthreads(); }
    float rstd = rsqrtf(red[0] * (1.0f / E_) + LN_EPS);

#pragma unroll
    for (int i = 0; i < 3; i++) {
        int c = t + i * 256;
        float val = (v[i] - mean) * rstd * g[c] + b[c];
        if (outf) outf[c] = val;
        if (outh) outh[c] = hf1(val);
    }
}

// merged LN1 + LN2
__global__ void ln_qk(const float* __restrict__ x, const float* __restrict__ y,
                      const float* __restrict__ g1, const float* __restrict__ b1,
                      const float* __restrict__ g2, const float* __restrict__ b2,
                      float* __restrict__ xn, ushort_t* __restrict__ xnb,
                      float* __restrict__ ynf, ushort_t* __restrict__ ynb) {
    __shared__ float red[256];
    int row = blockIdx.x;
    int t = threadIdx.x;
    if (row < B_ * N_TOK) {
        ln_row(x + (size_t)row * E_, g1, b1, xn + (size_t)row * E_,
               xnb + (size_t)row * E_, red, t);
    } else {
        int r2 = row - B_ * N_TOK;
        ln_row(y + (size_t)r2 * E_, g2, b2, ynf ? ynf + (size_t)r2 * E_ : nullptr,
               ynb + (size_t)r2 * E_, red, t);
    }
}

__global__ void ln_kernel(const float* __restrict__ in, const float* __restrict__ g,
                          const float* __restrict__ b, float* __restrict__ outf,
                          ushort_t* __restrict__ outb) {
    __shared__ float red[256];
    int row = blockIdx.x;
    int t = threadIdx.x;
    ln_row(in + (size_t)row * E_, g, b, outf ? outf + (size_t)row * E_ : nullptr,
           outb ? outb + (size_t)row * E_ : nullptr, red, t);
}

// ---------------- softmax: fp16 logits in, fp16 probs out ------------------
// warp-shuffle reductions: 2 __syncthreads total.
__global__ void softmax_h(const ushort_t* __restrict__ Lg, ushort_t* __restrict__ P) {
    __shared__ float wmax[8], wsum[8];
    size_t row = blockIdx.x;
    int t = threadIdx.x;
    int lane = t & 31, wd = t >> 5;
    const uint2* p2 = reinterpret_cast<const uint2*>(Lg + row * (size_t)M_TOK);

    uint2 u = p2[t];
    float2 f0 = __half22float2(*reinterpret_cast<__half2*>(&u.x));
    float2 f1 = __half22float2(*reinterpret_cast<__half2*>(&u.y));
    float mx = fmaxf(fmaxf(f0.x, f0.y), fmaxf(f1.x, f1.y));
#pragma unroll
    for (int o = 16; o > 0; o >>= 1) mx = fmaxf(mx, __shfl_xor_sync(0xffffffffu, mx, o));
    if (lane == 0) wmax[wd] = mx;
    __syncthreads();
    float m = wmax[0];
#pragma unroll
    for (int j = 1; j < 8; j++) m = fmaxf(m, wmax[j]);

    float e0 = __expf(f0.x - m);
    float e1 = exp_fma(f0.y - m);
    float e2 = __expf(f1.x - m);
    float e3 = exp_fma(f1.y - m);
    float sm = (e0 + e1) + (e2 + e3);
#pragma unroll
    for (int o = 16; o > 0; o >>= 1) sm += __shfl_xor_sync(0xffffffffu, sm, o);
    if (lane == 0) wsum[wd] = sm;
    __syncthreads();
    float tot = 0.f;
#pragma unroll
    for (int j = 0; j < 8; j++) tot += wsum[j];
    float inv = 1.0f / tot;

    uint2 w = make_uint2(hf2(e0 * inv, e1 * inv), hf2(e2 * inv, e3 * inv));
    reinterpret_cast<uint2*>(P + row * (size_t)M_TOK)[t] = w;
}

// ---------------- transposes -----------------------------------------------
__global__ void transpose2b(const float* __restrict__ in, int ldin, long long zin,
                            ushort_t* __restrict__ out, int ldout, long long zout) {
    __shared__ float t[32][33];
    in  += (long long)blockIdx.z * zin;
    out += (long long)blockIdx.z * zout;
    int r0 = blockIdx.y * 32, c0 = blockIdx.x * 32;
    int x = threadIdx.x, y = threadIdx.y;
#pragma unroll
    for (int i = 0; i < 32; i += 8) t[y + i][x] = in[(size_t)(r0 + y + i) * ldin + c0 + x];
    __syncthreads();
#pragma unroll
    for (int i = 0; i < 32; i += 8) out[(size_t)(c0 + y + i) * ldout + r0 + x] = hf1(t[x][y + i]);
}

__global__ void transpose_wqk(const float* __restrict__ in0, const float* __restrict__ in1,
                              ushort_t* __restrict__ out) {
    __shared__ float t[32][33];
    const float* in = blockIdx.z ? in1 : in0;
    ushort_t* o = out + (size_t)blockIdx.z * L_ * E_;
    int r0 = blockIdx.y * 32, c0 = blockIdx.x * 32;
    int x = threadIdx.x, y = threadIdx.y;
#pragma unroll
    for (int i = 0; i < 32; i += 8) t[y + i][x] = in[(size_t)(r0 + y + i) * L_ + c0 + x];
    __syncthreads();
#pragma unroll
    for (int i = 0; i < 32; i += 8) o[(size_t)(c0 + y + i) * E_ + r0 + x] = hf1(t[x][y + i]);
}

__global__ void transpose2h(const ushort_t* __restrict__ in, int ldin, long long zin,
                            ushort_t* __restrict__ out, int ldout, long long zout) {
    __shared__ ushort_t t[32][34];
    in  += (long long)blockIdx.z * zin;
    out += (long long)blockIdx.z * zout;
    int r0 = blockIdx.y * 32, c0 = blockIdx.x * 32;
    int x = threadIdx.x, y = threadIdx.y;
#pragma unroll
    for (int i = 0; i < 32; i += 8) t[y + i][x] = in[(size_t)(r0 + y + i) * ldin + c0 + x];
    __syncthreads();
#pragma unroll
    for (int i = 0; i < 32; i += 8) out[(size_t)(c0 + y + i) * ldout + r0 + x] = t[x][y + i];
}

__global__ void prep_bias(const float* __restrict__ bq, const float* __restrict__ bk,
                          const float* __restrict__ bv) {
    int e = blockIdx.x * 256 + threadIdx.x;
    if (e >= E_) return;
    g_bqk[e] = bq[e];
    g_bqk[E_ + e] = bk[e];
    float s = 0.f;
#pragma unroll
    for (int h = 0; h < H_; h++) s += bv[h * E_ + e];
    g_bsum[e] = s;
}

// ---------------- fp16 GEMM: cp.async 3-stage BK=64 + ldmatrix + mma -------
// D = alpha * Aop @ Bop^T (fp16 K-major). CTA 128x128, 8 warps 4m x 2n.
// Smem per stage per operand: 128 rows x 128 B, swizzle seg^(row&7).
// Dynamic smem: 96 KB. OT: 0 = fp32 out, 1 = fp16 out.
#define STG  3
#define AST  16384u   // stage bytes (128 rows * 128 B)
#define GSM  (2 * STG * AST)

template <int OT, bool RELU>
__global__ __launch_bounds__(256, 2) void tgemm(
    int K, int zdiv,
    const ushort_t* __restrict__ A, int lda, long long sA1, long long sA2,
    const ushort_t* __restrict__ Bop, int ldb, long long sB1, long long sB2,
    void* Cop, int ldc, long long sC1, long long sC2,
    const float* __restrict__ bias, long long sBias,
    const float* __restrict__ res, int ldr, long long sR1, long long sR2,
    float alpha)
{
    extern __shared__ ushort_t Sm[];

    int tid = threadIdx.x;
    int wid = tid >> 5;
    int lane = tid & 31;
    int g = lane >> 2;
    int tig = lane & 3;
    int warp_m = wid & 3;
    int warp_n = wid >> 2;

    int z = blockIdx.z;
    long long zq = z / zdiv, zr = z % zdiv;
    A   += zq * sA1 + zr * sA2;
    Bop += zq * sB1 + zr * sB2;
    long long coff = zq * sC1 + zr * sC2;
    if (bias) bias += zq * sBias;
    if (res) res += zq * sR1 + zr * sR2;

    int brow = blockIdx.y * 128;
    int bcol = blockIdx.x * 128;

    uint32_t asA = (uint32_t)__cvta_generic_to_shared(&Sm[0]);
    uint32_t asB = asA + STG * AST;

    // staging: thread handles 4x16B segments of one row per operand per stage
    int r = tid >> 1;
    int sg0 = (tid & 1) * 4;
    uint32_t rm = (uint32_t)(r & 7);
    uint32_t dA[4], dB[4];
#pragma unroll
    for (int j = 0; j < 4; j++) {
        uint32_t off = (uint32_t)(r * 128) + (((uint32_t)(sg0 + j) ^ rm) << 4);
        dA[j] = asA + off;
        dB[j] = asB + off;
    }
    const ushort_t* Ag = A + (size_t)(brow + r) * lda + sg0 * 8;
    const ushort_t* Bg = Bop + (size_t)(bcol + r) * ldb + sg0 * 8;

    int nchunk = K >> 6;

#define ISSUE(s, chunk) do { \
        const ushort_t* _a = Ag + (size_t)(chunk) * 64; \
        const ushort_t* _b = Bg + (size_t)(chunk) * 64; \
        _Pragma("unroll") \
        for (int _j = 0; _j < 4; _j++) { \
            asm volatile("cp.async.cg.shared.global [%0], [%1], 16;" :: "r"(dA[_j] + (s) * AST), "l"(_a + _j * 8)); \
            asm volatile("cp.async.cg.shared.global [%0], [%1], 16;" :: "r"(dB[_j] + (s) * AST), "l"(_b + _j * 8)); \
        } \
    } while (0)

    ISSUE(0, 0);
    asm volatile("cp.async.commit_group;");
    if (nchunk > 1) ISSUE(1, 1);
    asm volatile("cp.async.commit_group;");

    // ldmatrix addressing
    int sub = lane >> 3, r8 = lane & 7;
    uint32_t aOff[2], aM[2], bOff[4], bM[4];
#pragma unroll
    for (int mi = 0; mi < 2; mi++) {
        int row = warp_m * 32 + mi * 16 + (sub & 1) * 8 + r8;
        aOff[mi] = asA + (uint32_t)(row * 128);
        aM[mi] = (uint32_t)(row & 7);
    }
#pragma unroll
    for (int nq = 0; nq < 4; nq++) {
        int row = warp_n * 64 + nq * 16 + (sub >> 1) * 8 + r8;
        bOff[nq] = asB + (uint32_t)(row * 128);
        bM[nq] = (uint32_t)(row & 7);
    }
    uint32_t segA = (uint32_t)(sub >> 1);
    uint32_t segB = (uint32_t)(sub & 1);

    float acc[2][8][4];
#pragma unroll
    for (int i = 0; i < 2; i++)
#pragma unroll
        for (int j = 0; j < 8; j++)
#pragma unroll
            for (int c = 0; c < 4; c++) acc[i][j][c] = 0.f;

    int s = 0;
    for (int i = 0; i < nchunk; i++) {
        if (i + 1 < nchunk) asm volatile("cp.async.wait_group 1;");
        else                asm volatile("cp.async.wait_group 0;");
        __syncthreads();
        uint32_t sb = (uint32_t)(s * AST);

#pragma unroll
        for (int hh = 0; hh < 4; hh++) {
            uint32_t a[2][4], b[4][4];
#pragma unroll
            for (int mi = 0; mi < 2; mi++)
                LDMX4(a[mi], aOff[mi] + sb + (((2 * hh + segA) ^ aM[mi]) << 4));
#pragma unroll
            for (int nq = 0; nq < 4; nq++)
                LDMX4(b[nq], bOff[nq] + sb + (((2 * hh + segB) ^ bM[nq]) << 4));

#pragma unroll
            for (int p = 0; p < 4; p++)
#pragma unroll
                for (int h2 = 0; h2 < 2; h2++) {
                    int nj = 2 * p + h2;
                    uint32_t b0 = b[p][h2 * 2], b1 = b[p][h2 * 2 + 1];
#pragma unroll
                    for (int mi = 0; mi < 2; mi++)
                        mma_f16(acc[mi][nj][0], acc[mi][nj][1], acc[mi][nj][2], acc[mi][nj][3],
                                a[mi][0], a[mi][1], a[mi][2], a[mi][3], b0, b1);
                }
        }

        if (i + 2 < nchunk) {
            int sn = s + 2; if (sn >= STG) sn -= STG;
            ISSUE(sn, i + 2);
        }
        asm volatile("cp.async.commit_group;");
        if (++s == STG) s = 0;
    }
#undef ISSUE

    // epilogue
    float*    Cf = (float*)Cop + coff;
    ushort_t* Ch = (ushort_t*)Cop + coff;
#pragma unroll
    for (int mi = 0; mi < 2; mi++) {
        int r0 = brow + warp_m * 32 + mi * 16 + g;
#pragma unroll
        for (int nj = 0; nj < 8; nj++) {
            int col = bcol + warp_n * 64 + nj * 8 + 2 * tig;
            float2 bl = bias ? *reinterpret_cast<const float2*>(bias + col)
                             : make_float2(0.f, 0.f);
            float v0 = acc[mi][nj][0] * alpha + bl.x;
            float v1 = acc[mi][nj][1] * alpha + bl.y;
            float v2 = acc[mi][nj][2] * alpha + bl.x;
            float v3 = acc[mi][nj][3] * alpha + bl.y;
            if (res) {
                float2 r0v = *reinterpret_cast<const float2*>(res + (size_t)r0 * ldr + col);
                float2 r1v = *reinterpret_cast<const float2*>(res + (size_t)(r0 + 8) * ldr + col);
                v0 += r0v.x; v1 += r0v.y; v2 += r1v.x; v3 += r1v.y;
            }
            if (RELU) {
                v0 = fmaxf(v0, 0.f); v1 = fmaxf(v1, 0.f);
                v2 = fmaxf(v2, 0.f); v3 = fmaxf(v3, 0.f);
            }
            if (OT == 0) {
                *reinterpret_cast<float2*>(Cf + (size_t)r0 * ldc + col) = make_float2(v0, v1);
                *reinterpret_cast<float2*>(Cf + (size_t)(r0 + 8) * ldc + col) = make_float2(v2, v3);
            } else {
                *reinterpret_cast<uint32_t*>(Ch + (size_t)r0 * ldc + col) = hf2(v0, v1);
                *reinterpret_cast<uint32_t*>(Ch + (size_t)(r0 + 8) * ldc + col) = hf2(v2, v3);
            }
        }
    }
}

// ---------------- launch ---------------------------------------------------
extern "C" void kernel_launch(void* const* d_in, const int* in_sizes, int n_in,
                              void* d_out, int out_size) {
    const float* x     = (const float*)d_in[0];
    const float* y     = (const float*)d_in[1];
    const float* ln1_g = (const float*)d_in[2];
    const float* ln1_b = (const float*)d_in[3];
    const float* ln2_g = (const float*)d_in[4];
    const float* ln2_b = (const float*)d_in[5];
    const float* ln3_g = (const float*)d_in[6];
    const float* ln3_b = (const float*)d_in[7];
    const float* wq    = (const float*)d_in[8];
    const float* bq    = (const float*)d_in[9];
    const float* wk    = (const float*)d_in[10];
    const float* bk    = (const float*)d_in[11];
    const float* wv    = (const float*)d_in[12];
    const float* bv    = (const float*)d_in[13];
    const float* w_in  = (const float*)d_in[14];
    const float* b_in  = (const float*)d_in[15];
    const float* w_out = (const float*)d_in[16];
    const float* b_out = (const float*)d_in[17];
    float* out = (float*)d_out;

    float *p_xn, *p_hn, *p_A, *p_bqk, *p_bsum;
    uint32_t *p_Ab, *p_xyb, *p_hnb, *p_qkb, *p_Cb, *p_ynT;
    uint32_t *p_wqkT, *p_winT, *p_woutT, *p_w2T;
    cudaGetSymbolAddress((void**)&p_xn,   g_xn);
    cudaGetSymbolAddress((void**)&p_hn,   g_hn);
    cudaGetSymbolAddress((void**)&p_A,    g_A);
    cudaGetSymbolAddress((void**)&p_Ab,   g_Ab);
    cudaGetSymbolAddress((void**)&p_xyb,  g_xyb);
    cudaGetSymbolAddress((void**)&p_hnb,  g_hnb);
    cudaGetSymbolAddress((void**)&p_qkb,  g_qkb);
    cudaGetSymbolAddress((void**)&p_Cb,   g_Cb);
    cudaGetSymbolAddress((void**)&p_ynT,  g_ynT);
    cudaGetSymbolAddress((void**)&p_wqkT, g_wqkT);
    cudaGetSymbolAddress((void**)&p_winT, g_winT);
    cudaGetSymbolAddress((void**)&p_woutT,g_woutT);
    cudaGetSymbolAddress((void**)&p_w2T,  g_w2T);
    cudaGetSymbolAddress((void**)&p_bqk,  g_bqk);
    cudaGetSymbolAddress((void**)&p_bsum, g_bsum);

    cudaFuncSetAttribute(tgemm<0, false>, cudaFuncAttributeMaxDynamicSharedMemorySize, GSM);
    cudaFuncSetAttribute(tgemm<1, false>, cudaFuncAttributeMaxDynamicSharedMemorySize, GSM);
    cudaFuncSetAttribute(tgemm<1, true>,  cudaFuncAttributeMaxDynamicSharedMemorySize, GSM);

    const int ROWS = B_ * N_TOK;               // 8192
    const size_t CH = (size_t)B_ * N_TOK * E_; // 6291456
    float* out2 = ((size_t)out_size >= 2 * CH) ? out + CH : nullptr;

    ushort_t* xnb = (ushort_t*)p_xyb;
    ushort_t* ynb = xnb + (size_t)ROWS * E_;
    ushort_t* qb  = (ushort_t*)p_qkb;
    ushort_t* kb  = qb + (size_t)ROWS * L_;
    float*    p_hpre = p_A;                 // reuse logits buffer (fp32 capacity)
    uint32_t* p_mid  = p_qkb;               // reuse q half after scores consumed

    dim3 tb(32, 8);

    // #1: LN1 + LN2 merged
    ln_qk<<<2 * ROWS, 256>>>(x, y, ln1_g, ln1_b, ln2_g, ln2_b,
                             p_xn, xnb, out2, ynb);

    // #2: wq|wk transpose merged; #3: bias prep
    transpose_wqk<<<dim3(24, 24, 2), tb>>>(wq, wk, (ushort_t*)p_wqkT);
    prep_bias<<<3, 256>>>(bq, bk, bv);

    // #4: q|k projection, batched z=2
    tgemm<1, false><<<dim3(6, 64, 2), 256, GSM>>>(
        E_, 1,
        xnb, E_, (long long)ROWS * E_, 0,
        (ushort_t*)p_wqkT, E_, (long long)L_ * E_, 0,
        p_qkb, L_, (long long)ROWS * L_, 0,
        p_bqk, L_, nullptr, 0, 0, 0, 1.0f);

    // #5: scores -> fp16 logits, alpha = 1/8
    tgemm<1, false><<<dim3(8, 8, B_ * H_), 256, GSM>>>(
        HD_, H_,
        qb, L_, (long long)N_TOK * L_, HD_,
        kb, L_, (long long)M_TOK * L_, HD_,
        p_A, M_TOK, (long long)H_ * N_TOK * M_TOK, (long long)N_TOK * M_TOK,
        nullptr, 0, nullptr, 0, 0, 0, 0.125f);

    // #6: softmax
    softmax_h<<<B_ * H_ * N_TOK, 256>>>((ushort_t*)p_A, (ushort_t*)p_Ab);

    // remaining prep
    transpose2h<<<dim3(24, 32, B_), tb>>>(ynb, E_, (long long)M_TOK * E_,
                                           (ushort_t*)p_ynT, M_TOK, (long long)E_ * M_TOK);
    transpose2b<<<dim3(24, 24, H_), tb>>>(wv, H_ * E_, E_, (ushort_t*)p_w2T, H_ * E_, E_);
    transpose2b<<<dim3(24, 24, 1), tb>>>(w_in,  L_, 0, (ushort_t*)p_winT,  E_, 0);
    transpose2b<<<dim3(24, 24, 1), tb>>>(w_out, E_, 0, (ushort_t*)p_woutT, L_, 0);

    // C = A_h @ yn : fp16 -> fp16
    tgemm<1, false><<<dim3(6, 8, B_ * H_), 256, GSM>>>(
        M_TOK, H_,
        (ushort_t*)p_Ab, M_TOK, (long long)H_ * N_TOK * M_TOK, (long long)N_TOK * M_TOK,
        (ushort_t*)p_ynT, M_TOK, (long long)E_ * M_TOK, 0,
        p_Cb, H_ * E_, (long long)N_TOK * H_ * E_, E_,
        nullptr, 0, nullptr, 0, 0, 0, 1.0f);

    // h_pre = xn + C @ W2 + bsum : fp16 -> fp32
    tgemm<0, false><<<dim3(6, 64, 1), 256, GSM>>>(
        H_ * E_, 1,
        (ushort_t*)p_Cb, H_ * E_, 0, 0,
        (ushort_t*)p_w2T, H_ * E_, 0, 0,
        p_hpre, E_, 0, 0,
        p_bsum, 0, p_xn, E_, 0, 0, 1.0f);

    // LN3 -> fp32 + fp16
    ln_kernel<<<ROWS, 256>>>(p_hpre, ln3_g, ln3_b, p_hn, (ushort_t*)p_hnb);

    // mid = relu(hn @ w_in + b_in) -> fp16
    tgemm<1, true><<<dim3(6, 64, 1), 256, GSM>>>(
        E_, 1,
        (ushort_t*)p_hnb, E_, 0, 0,
        (ushort_t*)p_winT, E_, 0, 0,
        p_mid, L_, 0, 0,
        b_in, 0, nullptr, 0, 0, 0, 1.0f);

    // out = hn + mid @ w_out + b_out -> fp32 into d_out
    tgemm<0, false><<<dim3(6, 64, 1), 256, GSM>>>(
        L_, 1,
        (ushort_t*)p_mid, L_, 0, 0,
        (ushort_t*)p_woutT, L_, 0, 0,
        out, E_, 0, 0,
        b_out, 0, p_hn, E_, 0, 0, 1.0f);
}

// round 12
// speedup vs baseline: 1.0780x; 1.0780x over previous
#include <cuda_runtime.h>
#include <cuda_fp16.h>
#include <cstdint>
#include <cstdio>

typedef unsigned short ushort_t;

// Problem constants
#define B_    8
#define N_TOK 1024
#define M_TOK 1024
#define E_    768
#define L_    768
#define H_    12
#define HD_   64
#define LN_EPS 1e-5f

// ---------------- scratch (static __device__ — no allocations allowed) -----
__device__ float    g_xn [B_ * N_TOK * E_];                     // fp32 (residual)
__device__ float    g_hn [B_ * N_TOK * E_];                     // fp32 (residual)
__device__ float    g_A  [(size_t)B_ * H_ * N_TOK * M_TOK];     // fp16 logits / fp32 hpre
__device__ uint32_t g_Ab [(size_t)B_ * H_ * N_TOK * M_TOK / 2]; // fp16 probs
__device__ uint32_t g_xyb[2 * B_ * N_TOK * E_ / 2];             // fp16 xn | yn
__device__ uint32_t g_hnb[B_ * N_TOK * E_ / 2];                 // fp16 hn
__device__ uint32_t g_qkb[2 * B_ * N_TOK * L_ / 2];             // fp16 q | k (q half reused: mid)
__device__ uint32_t g_Cb [(size_t)B_ * N_TOK * H_ * E_ / 2];    // C fp16
__device__ uint32_t g_ynT[B_ * E_ * M_TOK / 2];                 // ynT fp16
__device__ uint32_t g_wqkT[2 * L_ * E_ / 2];                    // wqT | wkT
__device__ uint32_t g_wioT[2 * L_ * E_ / 2];                    // winT | woutT
__device__ uint32_t g_w2T [E_ * H_ * E_ / 2];
__device__ float    g_bqk[2 * L_];                              // bq | bk
__device__ float    g_bsum[E_];

// ---------------- fp16 helpers ---------------------------------------------
__device__ __forceinline__ uint32_t hf2(float lo, float hi) {
    uint32_t r;
    asm("cvt.rn.f16x2.f32 %0, %1, %2;" : "=r"(r) : "f"(hi), "f"(lo));
    return r;
}
__device__ __forceinline__ ushort_t hf1(float f) {
    ushort_t h; asm("cvt.rn.f16.f32 %0, %1;" : "=h"(h) : "f"(f)); return h;
}
__device__ __forceinline__ void mma_f16(float& c0, float& c1, float& c2, float& c3,
                                        uint32_t a0, uint32_t a1, uint32_t a2, uint32_t a3,
                                        uint32_t b0, uint32_t b1) {
    asm volatile(
        "mma.sync.aligned.m16n8k16.row.col.f32.f16.f16.f32 "
        "{%0,%1,%2,%3}, {%4,%5,%6,%7}, {%8,%9}, {%0,%1,%2,%3};"
        : "+f"(c0), "+f"(c1), "+f"(c2), "+f"(c3)
        : "r"(a0), "r"(a1), "r"(a2), "r"(a3), "r"(b0), "r"(b1));
}
#define LDMX4(rg, addr) \
    asm volatile("ldmatrix.sync.aligned.m8n8.x4.shared.b16 {%0,%1,%2,%3}, [%4];" \
        : "=r"((rg)[0]), "=r"((rg)[1]), "=r"((rg)[2]), "=r"((rg)[3]) : "r"(addr))

// FMA-pipe exp
__device__ __forceinline__ float exp_fma(float d) {
    float z = fmaxf(d * 1.44269504f, -125.0f);
    float y = z + 12582912.0f;
    float r = y - 12582912.0f;
    float f = z - r;
    float p = 1.33335581e-3f;
    p = p * f + 9.61812910e-3f;
    p = p * f + 5.55041087e-2f;
    p = p * f + 2.40226507e-1f;
    p = p * f + 6.93147180e-1f;
    p = p * f + 1.0f;
    int iy = __float_as_int(y);
    return __int_as_float(__float_as_int(p) + (iy << 23));
}

// ---------------- LayerNorm core -------------------------------------------
__device__ __forceinline__ void ln_row(const float* __restrict__ x,
                                       const float* __restrict__ g,
                                       const float* __restrict__ b,
                                       float* __restrict__ outf,
                                       ushort_t* __restrict__ outh,
                                       float* red, int t) {
    float v[3];
    float s = 0.f;
#pragma unroll
    for (int i = 0; i < 3; i++) { v[i] = x[t + i * 256]; s += v[i]; }
    red[t] = s; __syncthreads();
    for (int st = 128; st > 0; st >>= 1) { if (t < st) red[t] += red[t + st]; __syncthreads(); }
    float mean = red[0] * (1.0f / E_); __syncthreads();

    float sq = 0.f;
#pragma unroll
    for (int i = 0; i < 3; i++) { float d = v[i] - mean; sq += d * d; }
    red[t] = sq; __syncthreads();
    for (int st = 128; st > 0; st >>= 1) { if (t < st) red[t] += red[t + st]; __syncthreads(); }
    float rstd = rsqrtf(red[0] * (1.0f / E_) + LN_EPS);

#pragma unroll
    for (int i = 0; i < 3; i++) {
        int c = t + i * 256;
        float val = (v[i] - mean) * rstd * g[c] + b[c];
        if (outf) outf[c] = val;
        if (outh) outh[c] = hf1(val);
    }
}

// merged LN1 + LN2
__global__ void ln_qk(const float* __restrict__ x, const float* __restrict__ y,
                      const float* __restrict__ g1, const float* __restrict__ b1,
                      const float* __restrict__ g2, const float* __restrict__ b2,
                      float* __restrict__ xn, ushort_t* __restrict__ xnb,
                      float* __restrict__ ynf, ushort_t* __restrict__ ynb) {
    __shared__ float red[256];
    int row = blockIdx.x;
    int t = threadIdx.x;
    if (row < B_ * N_TOK) {
        ln_row(x + (size_t)row * E_, g1, b1, xn + (size_t)row * E_,
               xnb + (size_t)row * E_, red, t);
    } else {
        int r2 = row - B_ * N_TOK;
        ln_row(y + (size_t)r2 * E_, g2, b2, ynf ? ynf + (size_t)r2 * E_ : nullptr,
               ynb + (size_t)r2 * E_, red, t);
    }
}

__global__ void ln_kernel(const float* __restrict__ in, const float* __restrict__ g,
                          const float* __restrict__ b, float* __restrict__ outf,
                          ushort_t* __restrict__ outb) {
    __shared__ float red[256];
    int row = blockIdx.x;
    int t = threadIdx.x;
    ln_row(in + (size_t)row * E_, g, b, outf ? outf + (size_t)row * E_ : nullptr,
           outb ? outb + (size_t)row * E_ : nullptr, red, t);
}

// ---------------- softmax: fp16 logits in, fp16 probs out ------------------
// warp-shuffle reductions: 2 __syncthreads total.
__global__ void softmax_h(const ushort_t* __restrict__ Lg, ushort_t* __restrict__ P) {
    __shared__ float wmax[8], wsum[8];
    size_t row = blockIdx.x;
    int t = threadIdx.x;
    int lane = t & 31, wd = t >> 5;
    const uint2* p2 = reinterpret_cast<const uint2*>(Lg + row * (size_t)M_TOK);

    uint2 u = p2[t];
    float2 f0 = __half22float2(*reinterpret_cast<__half2*>(&u.x));
    float2 f1 = __half22float2(*reinterpret_cast<__half2*>(&u.y));
    float mx = fmaxf(fmaxf(f0.x, f0.y), fmaxf(f1.x, f1.y));
#pragma unroll
    for (int o = 16; o > 0; o >>= 1) mx = fmaxf(mx, __shfl_xor_sync(0xffffffffu, mx, o));
    if (lane == 0) wmax[wd] = mx;
    __syncthreads();
    float m = wmax[0];
#pragma unroll
    for (int j = 1; j < 8; j++) m = fmaxf(m, wmax[j]);

    float e0 = __expf(f0.x - m);
    float e1 = exp_fma(f0.y - m);
    float e2 = __expf(f1.x - m);
    float e3 = exp_fma(f1.y - m);
    float sm = (e0 + e1) + (e2 + e3);
#pragma unroll
    for (int o = 16; o > 0; o >>= 1) sm += __shfl_xor_sync(0xffffffffu, sm, o);
    if (lane == 0) wsum[wd] = sm;
    __syncthreads();
    float tot = 0.f;
#pragma unroll
    for (int j = 0; j < 8; j++) tot += wsum[j];
    float inv = 1.0f / tot;

    uint2 w = make_uint2(hf2(e0 * inv, e1 * inv), hf2(e2 * inv, e3 * inv));
    reinterpret_cast<uint2*>(P + row * (size_t)M_TOK)[t] = w;
}

// ---------------- transposes -----------------------------------------------
__global__ void transpose2b(const float* __restrict__ in, int ldin, long long zin,
                            ushort_t* __restrict__ out, int ldout, long long zout) {
    __shared__ float t[32][33];
    in  += (long long)blockIdx.z * zin;
    out += (long long)blockIdx.z * zout;
    int r0 = blockIdx.y * 32, c0 = blockIdx.x * 32;
    int x = threadIdx.x, y = threadIdx.y;
#pragma unroll
    for (int i = 0; i < 32; i += 8) t[y + i][x] = in[(size_t)(r0 + y + i) * ldin + c0 + x];
    __syncthreads();
#pragma unroll
    for (int i = 0; i < 32; i += 8) out[(size_t)(c0 + y + i) * ldout + r0 + x] = hf1(t[x][y + i]);
}

// dual 768x768 weight transpose (z selects src/dst pair)
__global__ void transpose_pair(const float* __restrict__ in0, const float* __restrict__ in1,
                               ushort_t* __restrict__ out) {
    __shared__ float t[32][33];
    const float* in = blockIdx.z ? in1 : in0;
    ushort_t* o = out + (size_t)blockIdx.z * L_ * E_;
    int r0 = blockIdx.y * 32, c0 = blockIdx.x * 32;
    int x = threadIdx.x, y = threadIdx.y;
#pragma unroll
    for (int i = 0; i < 32; i += 8) t[y + i][x] = in[(size_t)(r0 + y + i) * L_ + c0 + x];
    __syncthreads();
#pragma unroll
    for (int i = 0; i < 32; i += 8) o[(size_t)(c0 + y + i) * E_ + r0 + x] = hf1(t[x][y + i]);
}

__global__ void transpose2h(const ushort_t* __restrict__ in, int ldin, long long zin,
                            ushort_t* __restrict__ out, int ldout, long long zout) {
    __shared__ ushort_t t[32][34];
    in  += (long long)blockIdx.z * zin;
    out += (long long)blockIdx.z * zout;
    int r0 = blockIdx.y * 32, c0 = blockIdx.x * 32;
    int x = threadIdx.x, y = threadIdx.y;
#pragma unroll
    for (int i = 0; i < 32; i += 8) t[y + i][x] = in[(size_t)(r0 + y + i) * ldin + c0 + x];
    __syncthreads();
#pragma unroll
    for (int i = 0; i < 32; i += 8) out[(size_t)(c0 + y + i) * ldout + r0 + x] = t[x][y + i];
}

__global__ void prep_bias(const float* __restrict__ bq, const float* __restrict__ bk,
                          const float* __restrict__ bv) {
    int e = blockIdx.x * 256 + threadIdx.x;
    if (e >= E_) return;
    g_bqk[e] = bq[e];
    g_bqk[E_ + e] = bk[e];
    float s = 0.f;
#pragma unroll
    for (int h = 0; h < H_; h++) s += bv[h * E_ + e];
    g_bsum[e] = s;
}

// ---------------- fp16 GEMM: cp.async 3-stage BK=32 + ldmatrix + mma -------
// (exact R8 configuration — measured best)
// D = alpha * Aop @ Bop^T (fp16 K-major). CTA 128x128, 8 warps 4m x 2n.
// Smem per stage per operand: 128 rows x 64B, XOR swizzle seg^((row>>1)&3).
// OT: 0 = fp32 out, 1 = fp16 out.
#define STG  3
#define AST  8192u    // stage bytes (128 * 64)

template <int OT, bool RELU>
__global__ __launch_bounds__(256, 2) void tgemm(
    int K, int zdiv,
    const ushort_t* __restrict__ A, int lda, long long sA1, long long sA2,
    const ushort_t* __restrict__ Bop, int ldb, long long sB1, long long sB2,
    void* Cop, int ldc, long long sC1, long long sC2,
    const float* __restrict__ bias, long long sBias,
    const float* __restrict__ res, int ldr, long long sR1, long long sR2,
    float alpha)
{
    __shared__ ushort_t Sm[(2 * STG * AST) / 2];   // 48 KB

    int tid = threadIdx.x;
    int wid = tid >> 5;
    int lane = tid & 31;
    int g = lane >> 2;
    int tig = lane & 3;
    int warp_m = wid & 3;
    int warp_n = wid >> 2;

    int z = blockIdx.z;
    long long zq = z / zdiv, zr = z % zdiv;
    A   += zq * sA1 + zr * sA2;
    Bop += zq * sB1 + zr * sB2;
    long long coff = zq * sC1 + zr * sC2;
    if (bias) bias += zq * sBias;
    if (res) res += zq * sR1 + zr * sR2;

    int brow = blockIdx.y * 128;
    int bcol = blockIdx.x * 128;

    uint32_t asA = (uint32_t)__cvta_generic_to_shared(&Sm[0]);
    uint32_t asB = asA + STG * AST;

    // staging: thread handles 2x16B of one row per operand per stage
    int r = tid >> 1;
    int sg0 = (tid & 1) * 2;
    uint32_t swzS = (uint32_t)((r >> 1) & 3);
    uint32_t dA0 = asA + r * 64 + ((sg0 ^ swzS)) * 16;
    uint32_t dA1 = asA + r * 64 + (((sg0 + 1) ^ swzS)) * 16;
    uint32_t dB0 = dA0 + STG * AST;
    uint32_t dB1 = dA1 + STG * AST;
    const ushort_t* Ag = A + (size_t)(brow + r) * lda + sg0 * 8;
    const ushort_t* Bg = Bop + (size_t)(bcol + r) * ldb + sg0 * 8;

    int nchunk = K >> 5;

#define ISSUE(s, chunk) do { \
        const ushort_t* _a = Ag + (size_t)(chunk) * 32; \
        const ushort_t* _b = Bg + (size_t)(chunk) * 32; \
        asm volatile("cp.async.cg.shared.global [%0], [%1], 16;" :: "r"(dA0 + (s) * AST), "l"(_a)); \
        asm volatile("cp.async.cg.shared.global [%0], [%1], 16;" :: "r"(dA1 + (s) * AST), "l"(_a + 8)); \
        asm volatile("cp.async.cg.shared.global [%0], [%1], 16;" :: "r"(dB0 + (s) * AST), "l"(_b)); \
        asm volatile("cp.async.cg.shared.global [%0], [%1], 16;" :: "r"(dB1 + (s) * AST), "l"(_b + 8)); \
    } while (0)

    ISSUE(0, 0);
    asm volatile("cp.async.commit_group;");
    if (nchunk > 1) ISSUE(1, 1);
    asm volatile("cp.async.commit_group;");

    // ldmatrix addressing
    int sub = lane >> 3, r8 = lane & 7;
    uint32_t aBase[2], aSwz[2], bBase[4], bSwz[4];
#pragma unroll
    for (int mi = 0; mi < 2; mi++) {
        int row = warp_m * 32 + mi * 16 + (sub & 1) * 8 + r8;
        aBase[mi] = asA + row * 64;
        aSwz[mi] = (uint32_t)((row >> 1) & 3);
    }
#pragma unroll
    for (int nq = 0; nq < 4; nq++) {
        int row = warp_n * 64 + nq * 16 + (sub >> 1) * 8 + r8;
        bBase[nq] = asB + row * 64;
        bSwz[nq] = (uint32_t)((row >> 1) & 3);
    }
    uint32_t segA = (uint32_t)(sub >> 1);
    uint32_t segB = (uint32_t)(sub & 1);

    float acc[2][8][4];
#pragma unroll
    for (int i = 0; i < 2; i++)
#pragma unroll
        for (int j = 0; j < 8; j++)
#pragma unroll
            for (int c = 0; c < 4; c++) acc[i][j][c] = 0.f;

    int s = 0;
    for (int i = 0; i < nchunk; i++) {
        asm volatile("cp.async.wait_group 1;");
        __syncthreads();
        uint32_t sb = (uint32_t)(s * AST);

#pragma unroll
        for (int h = 0; h < 2; h++) {
            uint32_t a[2][4], b[4][4];
#pragma unroll
            for (int mi = 0; mi < 2; mi++)
                LDMX4(a[mi], aBase[mi] + sb + (((2 * h + segA) ^ aSwz[mi]) << 4));
#pragma unroll
            for (int nq = 0; nq < 4; nq++)
                LDMX4(b[nq], bBase[nq] + sb + (((2 * h + segB) ^ bSwz[nq]) << 4));

#pragma unroll
            for (int p = 0; p < 4; p++)
#pragma unroll
                for (int h2 = 0; h2 < 2; h2++) {
                    int nj = 2 * p + h2;
                    uint32_t b0 = b[p][h2 * 2], b1 = b[p][h2 * 2 + 1];
#pragma unroll
                    for (int mi = 0; mi < 2; mi++)
                        mma_f16(acc[mi][nj][0], acc[mi][nj][1], acc[mi][nj][2], acc[mi][nj][3],
                                a[mi][0], a[mi][1], a[mi][2], a[mi][3], b0, b1);
                }
        }

        if (i + 2 < nchunk) {
            int sn = s + 2; if (sn >= STG) sn -= STG;
            ISSUE(sn, i + 2);
        }
        asm volatile("cp.async.commit_group;");
        if (++s == STG) s = 0;
    }
#undef ISSUE

    // epilogue
    float*    Cf = (float*)Cop + coff;
    ushort_t* Ch = (ushort_t*)Cop + coff;
#pragma unroll
    for (int mi = 0; mi < 2; mi++) {
        int r0 = brow + warp_m * 32 + mi * 16 + g;
#pragma unroll
        for (int nj = 0; nj < 8; nj++) {
            int col = bcol + warp_n * 64 + nj * 8 + 2 * tig;
            float2 bl = bias ? *reinterpret_cast<const float2*>(bias + col)
                             : make_float2(0.f, 0.f);
            float v0 = acc[mi][nj][0] * alpha + bl.x;
            float v1 = acc[mi][nj][1] * alpha + bl.y;
            float v2 = acc[mi][nj][2] * alpha + bl.x;
            float v3 = acc[mi][nj][3] * alpha + bl.y;
            if (res) {
                float2 r0v = *reinterpret_cast<const float2*>(res + (size_t)r0 * ldr + col);
                float2 r1v = *reinterpret_cast<const float2*>(res + (size_t)(r0 + 8) * ldr + col);
                v0 += r0v.x; v1 += r0v.y; v2 += r1v.x; v3 += r1v.y;
            }
            if (RELU) {
                v0 = fmaxf(v0, 0.f); v1 = fmaxf(v1, 0.f);
                v2 = fmaxf(v2, 0.f); v3 = fmaxf(v3, 0.f);
            }
            if (OT == 0) {
                *reinterpret_cast<float2*>(Cf + (size_t)r0 * ldc + col) = make_float2(v0, v1);
                *reinterpret_cast<float2*>(Cf + (size_t)(r0 + 8) * ldc + col) = make_float2(v2, v3);
            } else {
                *reinterpret_cast<uint32_t*>(Ch + (size_t)r0 * ldc + col) = hf2(v0, v1);
                *reinterpret_cast<uint32_t*>(Ch + (size_t)(r0 + 8) * ldc + col) = hf2(v2, v3);
            }
        }
    }
}

// ---------------- launch ---------------------------------------------------
extern "C" void kernel_launch(void* const* d_in, const int* in_sizes, int n_in,
                              void* d_out, int out_size) {
    const float* x     = (const float*)d_in[0];
    const float* y     = (const float*)d_in[1];
    const float* ln1_g = (const float*)d_in[2];
    const float* ln1_b = (const float*)d_in[3];
    const float* ln2_g = (const float*)d_in[4];
    const float* ln2_b = (const float*)d_in[5];
    const float* ln3_g = (const float*)d_in[6];
    const float* ln3_b = (const float*)d_in[7];
    const float* wq    = (const float*)d_in[8];
    const float* bq    = (const float*)d_in[9];
    const float* wk    = (const float*)d_in[10];
    const float* bk    = (const float*)d_in[11];
    const float* wv    = (const float*)d_in[12];
    const float* bv    = (const float*)d_in[13];
    const float* w_in  = (const float*)d_in[14];
    const float* b_in  = (const float*)d_in[15];
    const float* w_out = (const float*)d_in[16];
    const float* b_out = (const float*)d_in[17];
    float* out = (float*)d_out;

    float *p_xn, *p_hn, *p_A, *p_bqk, *p_bsum;
    uint32_t *p_Ab, *p_xyb, *p_hnb, *p_qkb, *p_Cb, *p_ynT;
    uint32_t *p_wqkT, *p_wioT, *p_w2T;
    cudaGetSymbolAddress((void**)&p_xn,   g_xn);
    cudaGetSymbolAddress((void**)&p_hn,   g_hn);
    cudaGetSymbolAddress((void**)&p_A,    g_A);
    cudaGetSymbolAddress((void**)&p_Ab,   g_Ab);
    cudaGetSymbolAddress((void**)&p_xyb,  g_xyb);
    cudaGetSymbolAddress((void**)&p_hnb,  g_hnb);
    cudaGetSymbolAddress((void**)&p_qkb,  g_qkb);
    cudaGetSymbolAddress((void**)&p_Cb,   g_Cb);
    cudaGetSymbolAddress((void**)&p_ynT,  g_ynT);
    cudaGetSymbolAddress((void**)&p_wqkT, g_wqkT);
    cudaGetSymbolAddress((void**)&p_wioT, g_wioT);
    cudaGetSymbolAddress((void**)&p_w2T,  g_w2T);
    cudaGetSymbolAddress((void**)&p_bqk,  g_bqk);
    cudaGetSymbolAddress((void**)&p_bsum, g_bsum);

    const int ROWS = B_ * N_TOK;               // 8192
    const size_t CH = (size_t)B_ * N_TOK * E_; // 6291456
    float* out2 = ((size_t)out_size >= 2 * CH) ? out + CH : nullptr;

    ushort_t* xnb = (ushort_t*)p_xyb;
    ushort_t* ynb = xnb + (size_t)ROWS * E_;
    ushort_t* qb  = (ushort_t*)p_qkb;
    ushort_t* kb  = qb + (size_t)ROWS * L_;
    ushort_t* winT  = (ushort_t*)p_wioT;
    ushort_t* woutT = winT + (size_t)L_ * E_;
    float*    p_hpre = p_A;                 // reuse logits buffer (fp32 capacity)
    uint32_t* p_mid  = p_qkb;               // reuse q half after scores consumed

    dim3 tb(32, 8);

    // #1: LN1 + LN2 merged
    ln_qk<<<2 * ROWS, 256>>>(x, y, ln1_g, ln1_b, ln2_g, ln2_b,
                             p_xn, xnb, out2, ynb);

    // #2: wq|wk transpose merged; #3: bias prep
    transpose_pair<<<dim3(24, 24, 2), tb>>>(wq, wk, (ushort_t*)p_wqkT);
    prep_bias<<<3, 256>>>(bq, bk, bv);

    // #4: q|k projection, batched z=2
    tgemm<1, false><<<dim3(6, 64, 2), 256>>>(
        E_, 1,
        xnb, E_, (long long)ROWS * E_, 0,
        (ushort_t*)p_wqkT, E_, (long long)L_ * E_, 0,
        p_qkb, L_, (long long)ROWS * L_, 0,
        p_bqk, L_, nullptr, 0, 0, 0, 1.0f);

    // #5: scores -> fp16 logits, alpha = 1/8
    tgemm<1, false><<<dim3(8, 8, B_ * H_), 256>>>(
        HD_, H_,
        qb, L_, (long long)N_TOK * L_, HD_,
        kb, L_, (long long)M_TOK * L_, HD_,
        p_A, M_TOK, (long long)H_ * N_TOK * M_TOK, (long long)N_TOK * M_TOK,
        nullptr, 0, nullptr, 0, 0, 0, 0.125f);

    // #6: softmax
    softmax_h<<<B_ * H_ * N_TOK, 256>>>((ushort_t*)p_A, (ushort_t*)p_Ab);

    // remaining prep
    transpose2h<<<dim3(24, 32, B_), tb>>>(ynb, E_, (long long)M_TOK * E_,
                                           (ushort_t*)p_ynT, M_TOK, (long long)E_ * M_TOK);
    transpose2b<<<dim3(24, 24, H_), tb>>>(wv, H_ * E_, E_, (ushort_t*)p_w2T, H_ * E_, E_);
    transpose_pair<<<dim3(24, 24, 2), tb>>>(w_in, w_out, (ushort_t*)p_wioT);

    // C = A_h @ yn : fp16 -> fp16
    tgemm<1, false><<<dim3(6, 8, B_ * H_), 256>>>(
        M_TOK, H_,
        (ushort_t*)p_Ab, M_TOK, (long long)H_ * N_TOK * M_TOK, (long long)N_TOK * M_TOK,
        (ushort_t*)p_ynT, M_TOK, (long long)E_ * M_TOK, 0,
        p_Cb, H_ * E_, (long long)N_TOK * H_ * E_, E_,
        nullptr, 0, nullptr, 0, 0, 0, 1.0f);

    // h_pre = xn + C @ W2 + bsum : fp16 -> fp32
    tgemm<0, false><<<dim3(6, 64, 1), 256>>>(
        H_ * E_, 1,
        (ushort_t*)p_Cb, H_ * E_, 0, 0,
        (ushort_t*)p_w2T, H_ * E_, 0, 0,
        p_hpre, E_, 0, 0,
        p_bsum, 0, p_xn, E_, 0, 0, 1.0f);

    // LN3 -> fp32 + fp16
    ln_kernel<<<ROWS, 256>>>(p_hpre, ln3_g, ln3_b, p_hn, (ushort_t*)p_hnb);

    // mid = relu(hn @ w_in + b_in) -> fp16
    tgemm<1, true><<<dim3(6, 64, 1), 256>>>(
        E_, 1,
        (ushort_t*)p_hnb, E_, 0, 0,
        winT, E_, 0, 0,
        p_mid, L_, 0, 0,
        b_in, 0, nullptr, 0, 0, 0, 1.0f);

    // out = hn + mid @ w_out + b_out -> fp32 into d_out
    tgemm<0, false><<<dim3(6, 64, 1), 256>>>(
        L_, 1,
        (ushort_t*)p_mid, L_, 0, 0,
        woutT, L_, 0, 0,
        out, E_, 0, 0,
        b_out, 0, p_hn, E_, 0, 0, 1.0f);
}

// round 14
// speedup vs baseline: 1.1517x; 1.0684x over previous
#include <cuda_runtime.h>
#include <cuda_fp16.h>
#include <cstdint>
#include <cstdio>

typedef unsigned short ushort_t;

// Problem constants
#define B_    8
#define N_TOK 1024
#define M_TOK 1024
#define E_    768
#define L_    768
#define H_    12
#define HD_   64
#define LN_EPS 1e-5f

// ---------------- scratch (static __device__ — no allocations allowed) -----
__device__ float    g_xn [B_ * N_TOK * E_];                     // fp32 (residual)
__device__ float    g_hn [B_ * N_TOK * E_];                     // fp32 (residual)
__device__ float    g_hpre[B_ * N_TOK * E_];                    // fp32 hpre
__device__ uint32_t g_Ab [(size_t)B_ * H_ * N_TOK * M_TOK / 2]; // fp16 expA (unnormalized)
__device__ uint32_t g_xyb[2 * B_ * N_TOK * E_ / 2];             // fp16 xn | yn
__device__ uint32_t g_hnb[B_ * N_TOK * E_ / 2];                 // fp16 hn
__device__ uint32_t g_qkb[2 * B_ * N_TOK * L_ / 2];             // fp16 q | k (q half reused: mid)
__device__ uint32_t g_Cb [(size_t)B_ * N_TOK * H_ * E_ / 2];    // C fp16
__device__ uint32_t g_ynT[B_ * E_ * M_TOK / 2];                 // ynT fp16
__device__ uint32_t g_wqkT[2 * L_ * E_ / 2];                    // wqT | wkT
__device__ uint32_t g_wioT[2 * L_ * E_ / 2];                    // winT | woutT
__device__ uint32_t g_w2T [E_ * H_ * E_ / 2];
__device__ float    g_rs [B_ * H_ * N_TOK];                     // softmax row sums
__device__ float    g_bqk[2 * L_];                              // bq | bk
__device__ float    g_bsum[E_];

// ---------------- fp16 helpers ---------------------------------------------
__device__ __forceinline__ uint32_t hf2(float lo, float hi) {
    uint32_t r;
    asm("cvt.rn.f16x2.f32 %0, %1, %2;" : "=r"(r) : "f"(hi), "f"(lo));
    return r;
}
__device__ __forceinline__ ushort_t hf1(float f) {
    ushort_t h; asm("cvt.rn.f16.f32 %0, %1;" : "=h"(h) : "f"(f)); return h;
}
__device__ __forceinline__ float h2f(ushort_t h) {
    return __half2float(*reinterpret_cast<const __half*>(&h));
}
__device__ __forceinline__ void mma_f16(float& c0, float& c1, float& c2, float& c3,
                                        uint32_t a0, uint32_t a1, uint32_t a2, uint32_t a3,
                                        uint32_t b0, uint32_t b1) {
    asm volatile(
        "mma.sync.aligned.m16n8k16.row.col.f32.f16.f16.f32 "
        "{%0,%1,%2,%3}, {%4,%5,%6,%7}, {%8,%9}, {%0,%1,%2,%3};"
        : "+f"(c0), "+f"(c1), "+f"(c2), "+f"(c3)
        : "r"(a0), "r"(a1), "r"(a2), "r"(a3), "r"(b0), "r"(b1));
}
#define LDMX4(rg, addr) \
    asm volatile("ldmatrix.sync.aligned.m8n8.x4.shared.b16 {%0,%1,%2,%3}, [%4];" \
        : "=r"((rg)[0]), "=r"((rg)[1]), "=r"((rg)[2]), "=r"((rg)[3]) : "r"(addr))

// FMA-pipe exp
__device__ __forceinline__ float exp_fma(float d) {
    float z = fmaxf(d * 1.44269504f, -125.0f);
    float y = z + 12582912.0f;
    float r = y - 12582912.0f;
    float f = z - r;
    float p = 1.33335581e-3f;
    p = p * f + 9.61812910e-3f;
    p = p * f + 5.55041087e-2f;
    p = p * f + 2.40226507e-1f;
    p = p * f + 6.93147180e-1f;
    p = p * f + 1.0f;
    int iy = __float_as_int(y);
    return __int_as_float(__float_as_int(p) + (iy << 23));
}

// ---------------- LayerNorm core -------------------------------------------
__device__ __forceinline__ void ln_row(const float* __restrict__ x,
                                       const float* __restrict__ g,
                                       const float* __restrict__ b,
                                       float* __restrict__ outf,
                                       ushort_t* __restrict__ outh,
                                       float* red, int t) {
    float v[3];
    float s = 0.f;
#pragma unroll
    for (int i = 0; i < 3; i++) { v[i] = x[t + i * 256]; s += v[i]; }
    red[t] = s; __syncthreads();
    for (int st = 128; st > 0; st >>= 1) { if (t < st) red[t] += red[t + st]; __syncthreads(); }
    float mean = red[0] * (1.0f / E_); __syncthreads();

    float sq = 0.f;
#pragma unroll
    for (int i = 0; i < 3; i++) { float d = v[i] - mean; sq += d * d; }
    red[t] = sq; __syncthreads();
    for (int st = 128; st > 0; st >>= 1) { if (t < st) red[t] += red[t + st]; __syncthreads(); }
    float rstd = rsqrtf(red[0] * (1.0f / E_) + LN_EPS);

#pragma unroll
    for (int i = 0; i < 3; i++) {
        int c = t + i * 256;
        float val = (v[i] - mean) * rstd * g[c] + b[c];
        if (outf) outf[c] = val;
        if (outh) outh[c] = hf1(val);
    }
}

// merged LN1 + LN2
__global__ void ln_qk(const float* __restrict__ x, const float* __restrict__ y,
                      const float* __restrict__ g1, const float* __restrict__ b1,
                      const float* __restrict__ g2, const float* __restrict__ b2,
                      float* __restrict__ xn, ushort_t* __restrict__ xnb,
                      float* __restrict__ ynf, ushort_t* __restrict__ ynb) {
    __shared__ float red[256];
    int row = blockIdx.x;
    int t = threadIdx.x;
    if (row < B_ * N_TOK) {
        ln_row(x + (size_t)row * E_, g1, b1, xn + (size_t)row * E_,
               xnb + (size_t)row * E_, red, t);
    } else {
        int r2 = row - B_ * N_TOK;
        ln_row(y + (size_t)r2 * E_, g2, b2, ynf ? ynf + (size_t)r2 * E_ : nullptr,
               ynb + (size_t)r2 * E_, red, t);
    }
}

__global__ void ln_kernel(const float* __restrict__ in, const float* __restrict__ g,
                          const float* __restrict__ b, float* __restrict__ outf,
                          ushort_t* __restrict__ outb) {
    __shared__ float red[256];
    int row = blockIdx.x;
    int t = threadIdx.x;
    ln_row(in + (size_t)row * E_, g, b, outf ? outf + (size_t)row * E_ : nullptr,
           outb ? outb + (size_t)row * E_ : nullptr, red, t);
}

// ---------------- transposes -----------------------------------------------
__global__ void transpose2b(const float* __restrict__ in, int ldin, long long zin,
                            ushort_t* __restrict__ out, int ldout, long long zout) {
    __shared__ float t[32][33];
    in  += (long long)blockIdx.z * zin;
    out += (long long)blockIdx.z * zout;
    int r0 = blockIdx.y * 32, c0 = blockIdx.x * 32;
    int x = threadIdx.x, y = threadIdx.y;
#pragma unroll
    for (int i = 0; i < 32; i += 8) t[y + i][x] = in[(size_t)(r0 + y + i) * ldin + c0 + x];
    __syncthreads();
#pragma unroll
    for (int i = 0; i < 32; i += 8) out[(size_t)(c0 + y + i) * ldout + r0 + x] = hf1(t[x][y + i]);
}

// dual 768x768 weight transpose (z selects src/dst pair)
__global__ void transpose_pair(const float* __restrict__ in0, const float* __restrict__ in1,
                               ushort_t* __restrict__ out) {
    __shared__ float t[32][33];
    const float* in = blockIdx.z ? in1 : in0;
    ushort_t* o = out + (size_t)blockIdx.z * L_ * E_;
    int r0 = blockIdx.y * 32, c0 = blockIdx.x * 32;
    int x = threadIdx.x, y = threadIdx.y;
#pragma unroll
    for (int i = 0; i < 32; i += 8) t[y + i][x] = in[(size_t)(r0 + y + i) * L_ + c0 + x];
    __syncthreads();
#pragma unroll
    for (int i = 0; i < 32; i += 8) o[(size_t)(c0 + y + i) * E_ + r0 + x] = hf1(t[x][y + i]);
}

// fp16 -> fp16 transpose (ynT)
__global__ void transpose2h(const ushort_t* __restrict__ in, int ldin, long long zin,
                            ushort_t* __restrict__ out, int ldout, long long zout) {
    __shared__ ushort_t t[32][34];
    in  += (long long)blockIdx.z * zin;
    out += (long long)blockIdx.z * zout;
    int r0 = blockIdx.y * 32, c0 = blockIdx.x * 32;
    int x = threadIdx.x, y = threadIdx.y;
#pragma unroll
    for (int i = 0; i < 32; i += 8) t[y + i][x] = in[(size_t)(r0 + y + i) * ldin + c0 + x];
    __syncthreads();
#pragma unroll
    for (int i = 0; i < 32; i += 8) out[(size_t)(c0 + y + i) * ldout + r0 + x] = t[x][y + i];
}

__global__ void prep_bias(const float* __restrict__ bq, const float* __restrict__ bk,
                          const float* __restrict__ bv) {
    int e = blockIdx.x * 256 + threadIdx.x;
    if (e >= E_) return;
    g_bqk[e] = bq[e];
    g_bqk[E_ + e] = bk[e];
    float s = 0.f;
#pragma unroll
    for (int h = 0; h < H_; h++) s += bv[h * E_ + e];
    g_bsum[e] = s;
}

__global__ void zero_rs() {
    int i = blockIdx.x * 256 + threadIdx.x;
    if (i < B_ * H_ * N_TOK) g_rs[i] = 0.f;
}

// ---------------- fp16 GEMM: cp.async 3-stage BK=32 + ldmatrix + mma -------
// D = alpha * Aop @ Bop^T (fp16 K-major). CTA 128x128, 8 warps 4m x 2n.
// OM: 0 = fp32 out (+bias/res), 1 = fp16 out (+bias),
//     2 = exp(acc*alpha) -> fp16 out + row-sum atomics into rsum,
//     3 = fp16 out scaled per-row by 1/rsum[row].
// NOTE: for OM!=0, all C strides/ld are in ushort (fp16 element) units.
#define STG  3
#define AST  8192u    // stage bytes (128 * 64)

template <int OM, bool RELU>
__global__ __launch_bounds__(256, 2) void tgemm(
    int K, int zdiv,
    const ushort_t* __restrict__ A, int lda, long long sA1, long long sA2,
    const ushort_t* __restrict__ Bop, int ldb, long long sB1, long long sB2,
    void* Cop, int ldc, long long sC1, long long sC2,
    const float* __restrict__ bias, long long sBias,
    const float* __restrict__ res, int ldr, long long sR1, long long sR2,
    float* rsum,
    float alpha)
{
    __shared__ ushort_t Sm[(2 * STG * AST) / 2];   // 48 KB

    int tid = threadIdx.x;
    int wid = tid >> 5;
    int lane = tid & 31;
    int g = lane >> 2;
    int tig = lane & 3;
    int warp_m = wid & 3;
    int warp_n = wid >> 2;

    int z = blockIdx.z;
    long long zq = z / zdiv, zr = z % zdiv;
    A   += zq * sA1 + zr * sA2;
    Bop += zq * sB1 + zr * sB2;
    long long coff = zq * sC1 + zr * sC2;
    if (bias) bias += zq * sBias;
    if (res) res += zq * sR1 + zr * sR2;
    if (OM == 2 || OM == 3) rsum += (long long)z * N_TOK;

    int brow = blockIdx.y * 128;
    int bcol = blockIdx.x * 128;

    uint32_t asA = (uint32_t)__cvta_generic_to_shared(&Sm[0]);
    uint32_t asB = asA + STG * AST;

    // staging: thread handles 2x16B of one row per operand per stage
    int r = tid >> 1;
    int sg0 = (tid & 1) * 2;
    uint32_t swzS = (uint32_t)((r >> 1) & 3);
    uint32_t dA0 = asA + r * 64 + ((sg0 ^ swzS)) * 16;
    uint32_t dA1 = asA + r * 64 + (((sg0 + 1) ^ swzS)) * 16;
    uint32_t dB0 = dA0 + STG * AST;
    uint32_t dB1 = dA1 + STG * AST;
    const ushort_t* Ag = A + (size_t)(brow + r) * lda + sg0 * 8;
    const ushort_t* Bg = Bop + (size_t)(bcol + r) * ldb + sg0 * 8;

    int nchunk = K >> 5;

#define ISSUE(s, chunk) do { \
        const ushort_t* _a = Ag + (size_t)(chunk) * 32; \
        const ushort_t* _b = Bg + (size_t)(chunk) * 32; \
        asm volatile("cp.async.cg.shared.global [%0], [%1], 16;" :: "r"(dA0 + (s) * AST), "l"(_a)); \
        asm volatile("cp.async.cg.shared.global [%0], [%1], 16;" :: "r"(dA1 + (s) * AST), "l"(_a + 8)); \
        asm volatile("cp.async.cg.shared.global [%0], [%1], 16;" :: "r"(dB0 + (s) * AST), "l"(_b)); \
        asm volatile("cp.async.cg.shared.global [%0], [%1], 16;" :: "r"(dB1 + (s) * AST), "l"(_b + 8)); \
    } while (0)

    ISSUE(0, 0);
    asm volatile("cp.async.commit_group;");
    if (nchunk > 1) ISSUE(1, 1);
    asm volatile("cp.async.commit_group;");

    // ldmatrix addressing
    int sub = lane >> 3, r8 = lane & 7;
    uint32_t aBase[2], aSwz[2], bBase[4], bSwz[4];
#pragma unroll
    for (int mi = 0; mi < 2; mi++) {
        int row = warp_m * 32 + mi * 16 + (sub & 1) * 8 + r8;
        aBase[mi] = asA + row * 64;
        aSwz[mi] = (uint32_t)((row >> 1) & 3);
    }
#pragma unroll
    for (int nq = 0; nq < 4; nq++) {
        int row = warp_n * 64 + nq * 16 + (sub >> 1) * 8 + r8;
        bBase[nq] = asB + row * 64;
        bSwz[nq] = (uint32_t)((row >> 1) & 3);
    }
    uint32_t segA = (uint32_t)(sub >> 1);
    uint32_t segB = (uint32_t)(sub & 1);

    float acc[2][8][4];
#pragma unroll
    for (int i = 0; i < 2; i++)
#pragma unroll
        for (int j = 0; j < 8; j++)
#pragma unroll
            for (int c = 0; c < 4; c++) acc[i][j][c] = 0.f;

    int s = 0;
    for (int i = 0; i < nchunk; i++) {
        asm volatile("cp.async.wait_group 1;");
        __syncthreads();
        uint32_t sb = (uint32_t)(s * AST);

#pragma unroll
        for (int h = 0; h < 2; h++) {
            uint32_t a[2][4], b[4][4];
#pragma unroll
            for (int mi = 0; mi < 2; mi++)
                LDMX4(a[mi], aBase[mi] + sb + (((2 * h + segA) ^ aSwz[mi]) << 4));
#pragma unroll
            for (int nq = 0; nq < 4; nq++)
                LDMX4(b[nq], bBase[nq] + sb + (((2 * h + segB) ^ bSwz[nq]) << 4));

#pragma unroll
            for (int p = 0; p < 4; p++)
#pragma unroll
                for (int h2 = 0; h2 < 2; h2++) {
                    int nj = 2 * p + h2;
                    uint32_t b0 = b[p][h2 * 2], b1 = b[p][h2 * 2 + 1];
#pragma unroll
                    for (int mi = 0; mi < 2; mi++)
                        mma_f16(acc[mi][nj][0], acc[mi][nj][1], acc[mi][nj][2], acc[mi][nj][3],
                                a[mi][0], a[mi][1], a[mi][2], a[mi][3], b0, b1);
                }
        }

        if (i + 2 < nchunk) {
            int sn = s + 2; if (sn >= STG) sn -= STG;
            ISSUE(sn, i + 2);
        }
        asm volatile("cp.async.commit_group;");
        if (++s == STG) s = 0;
    }
#undef ISSUE

    // epilogue
    float*    Cf = (float*)Cop + coff;
    ushort_t* Ch = (ushort_t*)Cop + coff;

    if (OM == 2) {
        // exp + fp16 store + per-row sum atomics (sum the ROUNDED values)
#pragma unroll
        for (int mi = 0; mi < 2; mi++) {
            int r0 = brow + warp_m * 32 + mi * 16 + g;
            float s_lo = 0.f, s_hi = 0.f;
#pragma unroll
            for (int nj = 0; nj < 8; nj++) {
                int col = bcol + warp_n * 64 + nj * 8 + 2 * tig;
                float e0 = exp_fma(acc[mi][nj][0] * alpha);
                float e1 = exp_fma(acc[mi][nj][1] * alpha);
                float e2 = exp_fma(acc[mi][nj][2] * alpha);
                float e3 = exp_fma(acc[mi][nj][3] * alpha);
                uint32_t p0 = hf2(e0, e1);
                uint32_t p1 = hf2(e2, e3);
                s_lo += h2f((ushort_t)(p0 & 0xffff)) + h2f((ushort_t)(p0 >> 16));
                s_hi += h2f((ushort_t)(p1 & 0xffff)) + h2f((ushort_t)(p1 >> 16));
                *reinterpret_cast<uint32_t*>(Ch + (size_t)r0 * ldc + col) = p0;
                *reinterpret_cast<uint32_t*>(Ch + (size_t)(r0 + 8) * ldc + col) = p1;
            }
            s_lo += __shfl_xor_sync(0xffffffffu, s_lo, 1);
            s_lo += __shfl_xor_sync(0xffffffffu, s_lo, 2);
            s_hi += __shfl_xor_sync(0xffffffffu, s_hi, 1);
            s_hi += __shfl_xor_sync(0xffffffffu, s_hi, 2);
            if (tig == 0) {
                atomicAdd(&rsum[r0], s_lo);
                atomicAdd(&rsum[r0 + 8], s_hi);
            }
        }
        return;
    }

#pragma unroll
    for (int mi = 0; mi < 2; mi++) {
        int r0 = brow + warp_m * 32 + mi * 16 + g;
        float inv_lo = 1.f, inv_hi = 1.f;
        if (OM == 3) {
            inv_lo = 1.0f / rsum[r0];
            inv_hi = 1.0f / rsum[r0 + 8];
        }
#pragma unroll
        for (int nj = 0; nj < 8; nj++) {
            int col = bcol + warp_n * 64 + nj * 8 + 2 * tig;
            float2 bl = bias ? *reinterpret_cast<const float2*>(bias + col)
                             : make_float2(0.f, 0.f);
            float v0 = acc[mi][nj][0] * alpha + bl.x;
            float v1 = acc[mi][nj][1] * alpha + bl.y;
            float v2 = acc[mi][nj][2] * alpha + bl.x;
            float v3 = acc[mi][nj][3] * alpha + bl.y;
            if (OM == 3) {
                v0 *= inv_lo; v1 *= inv_lo;
                v2 *= inv_hi; v3 *= inv_hi;
            }
            if (res) {
                float2 r0v = *reinterpret_cast<const float2*>(res + (size_t)r0 * ldr + col);
                float2 r1v = *reinterpret_cast<const float2*>(res + (size_t)(r0 + 8) * ldr + col);
                v0 += r0v.x; v1 += r0v.y; v2 += r1v.x; v3 += r1v.y;
            }
            if (RELU) {
                v0 = fmaxf(v0, 0.f); v1 = fmaxf(v1, 0.f);
                v2 = fmaxf(v2, 0.f); v3 = fmaxf(v3, 0.f);
            }
            if (OM == 0) {
                *reinterpret_cast<float2*>(Cf + (size_t)r0 * ldc + col) = make_float2(v0, v1);
                *reinterpret_cast<float2*>(Cf + (size_t)(r0 + 8) * ldc + col) = make_float2(v2, v3);
            } else {
                *reinterpret_cast<uint32_t*>(Ch + (size_t)r0 * ldc + col) = hf2(v0, v1);
                *reinterpret_cast<uint32_t*>(Ch + (size_t)(r0 + 8) * ldc + col) = hf2(v2, v3);
            }
        }
    }
}

// ---------------- launch ---------------------------------------------------
extern "C" void kernel_launch(void* const* d_in, const int* in_sizes, int n_in,
                              void* d_out, int out_size) {
    const float* x     = (const float*)d_in[0];
    const float* y     = (const float*)d_in[1];
    const float* ln1_g = (const float*)d_in[2];
    const float* ln1_b = (const float*)d_in[3];
    const float* ln2_g = (const float*)d_in[4];
    const float* ln2_b = (const float*)d_in[5];
    const float* ln3_g = (const float*)d_in[6];
    const float* ln3_b = (const float*)d_in[7];
    const float* wq    = (const float*)d_in[8];
    const float* bq    = (const float*)d_in[9];
    const float* wk    = (const float*)d_in[10];
    const float* bk    = (const float*)d_in[11];
    const float* wv    = (const float*)d_in[12];
    const float* bv    = (const float*)d_in[13];
    const float* w_in  = (const float*)d_in[14];
    const float* b_in  = (const float*)d_in[15];
    const float* w_out = (const float*)d_in[16];
    const float* b_out = (const float*)d_in[17];
    float* out = (float*)d_out;

    float *p_xn, *p_hn, *p_hpre, *p_rs, *p_bqk, *p_bsum;
    uint32_t *p_Ab, *p_xyb, *p_hnb, *p_qkb, *p_Cb, *p_ynT;
    uint32_t *p_wqkT, *p_wioT, *p_w2T;
    cudaGetSymbolAddress((void**)&p_xn,   g_xn);
    cudaGetSymbolAddress((void**)&p_hn,   g_hn);
    cudaGetSymbolAddress((void**)&p_hpre, g_hpre);
    cudaGetSymbolAddress((void**)&p_Ab,   g_Ab);
    cudaGetSymbolAddress((void**)&p_xyb,  g_xyb);
    cudaGetSymbolAddress((void**)&p_hnb,  g_hnb);
    cudaGetSymbolAddress((void**)&p_qkb,  g_qkb);
    cudaGetSymbolAddress((void**)&p_Cb,   g_Cb);
    cudaGetSymbolAddress((void**)&p_ynT,  g_ynT);
    cudaGetSymbolAddress((void**)&p_wqkT, g_wqkT);
    cudaGetSymbolAddress((void**)&p_wioT, g_wioT);
    cudaGetSymbolAddress((void**)&p_w2T,  g_w2T);
    cudaGetSymbolAddress((void**)&p_rs,   g_rs);
    cudaGetSymbolAddress((void**)&p_bqk,  g_bqk);
    cudaGetSymbolAddress((void**)&p_bsum, g_bsum);

    const int ROWS = B_ * N_TOK;               // 8192
    const size_t CH = (size_t)B_ * N_TOK * E_; // 6291456
    float* out2 = ((size_t)out_size >= 2 * CH) ? out + CH : nullptr;

    ushort_t* xnb = (ushort_t*)p_xyb;
    ushort_t* ynb = xnb + (size_t)ROWS * E_;
    ushort_t* qb  = (ushort_t*)p_qkb;
    ushort_t* kb  = qb + (size_t)ROWS * L_;
    ushort_t* winT  = (ushort_t*)p_wioT;
    ushort_t* woutT = winT + (size_t)L_ * E_;
    uint32_t* p_mid = p_qkb;                // reuse q half after scores consumed

    dim3 tb(32, 8);

    // LN1 + LN2 merged
    ln_qk<<<2 * ROWS, 256>>>(x, y, ln1_g, ln1_b, ln2_g, ln2_b,
                             p_xn, xnb, out2, ynb);

    // wq|wk transpose merged; bias prep; rs zero
    transpose_pair<<<dim3(24, 24, 2), tb>>>(wq, wk, (ushort_t*)p_wqkT);
    prep_bias<<<3, 256>>>(bq, bk, bv);
    zero_rs<<<(B_ * H_ * N_TOK + 255) / 256, 256>>>();

    // q|k projection, batched z=2
    tgemm<1, false><<<dim3(6, 64, 2), 256>>>(
        E_, 1,
        xnb, E_, (long long)ROWS * E_, 0,
        (ushort_t*)p_wqkT, E_, (long long)L_ * E_, 0,
        p_qkb, L_, (long long)ROWS * L_, 0,
        p_bqk, L_, nullptr, 0, 0, 0, nullptr, 1.0f);

    // scores -> exp(logit) fp16 (unnormalized) + row-sum atomics, alpha = 1/8
    // C strides in ushort units.
    tgemm<2, false><<<dim3(8, 8, B_ * H_), 256>>>(
        HD_, H_,
        qb, L_, (long long)N_TOK * L_, HD_,
        kb, L_, (long long)M_TOK * L_, HD_,
        p_Ab, M_TOK, (long long)H_ * N_TOK * M_TOK, (long long)N_TOK * M_TOK,
        nullptr, 0, nullptr, 0, 0, 0, p_rs, 0.125f);

    // remaining prep (fills the dependency gap)
    transpose2h<<<dim3(24, 32, B_), tb>>>(ynb, E_, (long long)M_TOK * E_,
                                           (ushort_t*)p_ynT, M_TOK, (long long)E_ * M_TOK);
    transpose2b<<<dim3(24, 24, H_), tb>>>(wv, H_ * E_, E_, (ushort_t*)p_w2T, H_ * E_, E_);
    transpose_pair<<<dim3(24, 24, 2), tb>>>(w_in, w_out, (ushort_t*)p_wioT);

    // C = softmax(A)_h @ yn : fp16, per-row 1/rowsum scale -> fp16
    tgemm<3, false><<<dim3(6, 8, B_ * H_), 256>>>(
        M_TOK, H_,
        (ushort_t*)p_Ab, M_TOK, (long long)H_ * N_TOK * M_TOK, (long long)N_TOK * M_TOK,
        (ushort_t*)p_ynT, M_TOK, (long long)E_ * M_TOK, 0,
        p_Cb, H_ * E_, (long long)N_TOK * H_ * E_, E_,
        nullptr, 0, nullptr, 0, 0, 0, p_rs, 1.0f);

    // h_pre = xn + C @ W2 + bsum : fp16 -> fp32
    tgemm<0, false><<<dim3(6, 64, 1), 256>>>(
        H_ * E_, 1,
        (ushort_t*)p_Cb, H_ * E_, 0, 0,
        (ushort_t*)p_w2T, H_ * E_, 0, 0,
        p_hpre, E_, 0, 0,
        p_bsum, 0, p_xn, E_, 0, 0, nullptr, 1.0f);

    // LN3 -> fp32 + fp16
    ln_kernel<<<ROWS, 256>>>(p_hpre, ln3_g, ln3_b, p_hn, (ushort_t*)p_hnb);

    // mid = relu(hn @ w_in + b_in) -> fp16
    tgemm<1, true><<<dim3(6, 64, 1), 256>>>(
        E_, 1,
        (ushort_t*)p_hnb, E_, 0, 0,
        winT, E_, 0, 0,
        p_mid, L_, 0, 0,
        b_in, 0, nullptr, 0, 0, 0, nullptr, 1.0f);

    // out = hn + mid @ w_out + b_out -> fp32 into d_out
    tgemm<0, false><<<dim3(6, 64, 1), 256>>>(
        L_, 1,
        (ushort_t*)p_mid, L_, 0, 0,
        woutT, L_, 0, 0,
        out, E_, 0, 0,
        b_out, 0, p_hn, E_, 0, 0, nullptr, 1.0f);
}

// round 15
// speedup vs baseline: 1.1537x; 1.0017x over previous
#include <cuda_runtime.h>
#include <cuda_fp16.h>
#include <cstdint>
#include <cstdio>

typedef unsigned short ushort_t;

// Problem constants
#define B_    8
#define N_TOK 1024
#define M_TOK 1024
#define E_    768
#define L_    768
#define H_    12
#define HD_   64
#define LN_EPS 1e-5f

// ---------------- scratch (static __device__ — no allocations allowed) -----
__device__ float    g_xn [B_ * N_TOK * E_];                     // fp32 (residual)
__device__ float    g_hn [B_ * N_TOK * E_];                     // fp32 (residual)
__device__ float    g_hpre[B_ * N_TOK * E_];                    // fp32 hpre
__device__ uint32_t g_Ab [(size_t)B_ * H_ * N_TOK * M_TOK / 2]; // fp16 expA (unnormalized)
__device__ uint32_t g_xyb[2 * B_ * N_TOK * E_ / 2];             // fp16 xn | yn
__device__ uint32_t g_hnb[B_ * N_TOK * E_ / 2];                 // fp16 hn
__device__ uint32_t g_qkb[2 * B_ * N_TOK * L_ / 2];             // fp16 q | k (q half reused: mid)
__device__ uint32_t g_Cb [(size_t)B_ * N_TOK * H_ * E_ / 2];    // C fp16
__device__ uint32_t g_ynT[B_ * E_ * M_TOK / 2];                 // ynT fp16
__device__ uint32_t g_wqkT[2 * L_ * E_ / 2];                    // wqT | wkT
__device__ uint32_t g_wioT[2 * L_ * E_ / 2];                    // winT | woutT
__device__ uint32_t g_w2T [E_ * H_ * E_ / 2];
__device__ float    g_rs [B_ * H_ * N_TOK];                     // softmax row sums
__device__ float    g_bqk[2 * L_];                              // bq | bk
__device__ float    g_bsum[E_];

// ---------------- fp16 helpers ---------------------------------------------
__device__ __forceinline__ uint32_t hf2(float lo, float hi) {
    uint32_t r;
    asm("cvt.rn.f16x2.f32 %0, %1, %2;" : "=r"(r) : "f"(hi), "f"(lo));
    return r;
}
__device__ __forceinline__ ushort_t hf1(float f) {
    ushort_t h; asm("cvt.rn.f16.f32 %0, %1;" : "=h"(h) : "f"(f)); return h;
}
__device__ __forceinline__ float h2f(ushort_t h) {
    return __half2float(*reinterpret_cast<const __half*>(&h));
}
__device__ __forceinline__ void mma_f16(float& c0, float& c1, float& c2, float& c3,
                                        uint32_t a0, uint32_t a1, uint32_t a2, uint32_t a3,
                                        uint32_t b0, uint32_t b1) {
    asm volatile(
        "mma.sync.aligned.m16n8k16.row.col.f32.f16.f16.f32 "
        "{%0,%1,%2,%3}, {%4,%5,%6,%7}, {%8,%9}, {%0,%1,%2,%3};"
        : "+f"(c0), "+f"(c1), "+f"(c2), "+f"(c3)
        : "r"(a0), "r"(a1), "r"(a2), "r"(a3), "r"(b0), "r"(b1));
}
#define LDMX4(rg, addr) \
    asm volatile("ldmatrix.sync.aligned.m8n8.x4.shared.b16 {%0,%1,%2,%3}, [%4];" \
        : "=r"((rg)[0]), "=r"((rg)[1]), "=r"((rg)[2]), "=r"((rg)[3]) : "r"(addr))

// FMA-pipe exp
__device__ __forceinline__ float exp_fma(float d) {
    float z = fmaxf(d * 1.44269504f, -125.0f);
    float y = z + 12582912.0f;
    float r = y - 12582912.0f;
    float f = z - r;
    float p = 1.33335581e-3f;
    p = p * f + 9.61812910e-3f;
    p = p * f + 5.55041087e-2f;
    p = p * f + 2.40226507e-1f;
    p = p * f + 6.93147180e-1f;
    p = p * f + 1.0f;
    int iy = __float_as_int(y);
    return __int_as_float(__float_as_int(p) + (iy << 23));
}

// ---------------- LayerNorm core -------------------------------------------
__device__ __forceinline__ void ln_row(const float* __restrict__ x,
                                       const float* __restrict__ g,
                                       const float* __restrict__ b,
                                       float* __restrict__ outf,
                                       ushort_t* __restrict__ outh,
                                       float* red, int t) {
    float v[3];
    float s = 0.f;
#pragma unroll
    for (int i = 0; i < 3; i++) { v[i] = x[t + i * 256]; s += v[i]; }
    red[t] = s; __syncthreads();
    for (int st = 128; st > 0; st >>= 1) { if (t < st) red[t] += red[t + st]; __syncthreads(); }
    float mean = red[0] * (1.0f / E_); __syncthreads();

    float sq = 0.f;
#pragma unroll
    for (int i = 0; i < 3; i++) { float d = v[i] - mean; sq += d * d; }
    red[t] = sq; __syncthreads();
    for (int st = 128; st > 0; st >>= 1) { if (t < st) red[t] += red[t + st]; __syncthreads(); }
    float rstd = rsqrtf(red[0] * (1.0f / E_) + LN_EPS);

#pragma unroll
    for (int i = 0; i < 3; i++) {
        int c = t + i * 256;
        float val = (v[i] - mean) * rstd * g[c] + b[c];
        if (outf) outf[c] = val;
        if (outh) outh[c] = hf1(val);
    }
}

// merged LN1 + LN2
__global__ void ln_qk(const float* __restrict__ x, const float* __restrict__ y,
                      const float* __restrict__ g1, const float* __restrict__ b1,
                      const float* __restrict__ g2, const float* __restrict__ b2,
                      float* __restrict__ xn, ushort_t* __restrict__ xnb,
                      float* __restrict__ ynf, ushort_t* __restrict__ ynb) {
    __shared__ float red[256];
    int row = blockIdx.x;
    int t = threadIdx.x;
    if (row < B_ * N_TOK) {
        ln_row(x + (size_t)row * E_, g1, b1, xn + (size_t)row * E_,
               xnb + (size_t)row * E_, red, t);
    } else {
        int r2 = row - B_ * N_TOK;
        ln_row(y + (size_t)r2 * E_, g2, b2, ynf ? ynf + (size_t)r2 * E_ : nullptr,
               ynb + (size_t)r2 * E_, red, t);
    }
}

__global__ void ln_kernel(const float* __restrict__ in, const float* __restrict__ g,
                          const float* __restrict__ b, float* __restrict__ outf,
                          ushort_t* __restrict__ outb) {
    __shared__ float red[256];
    int row = blockIdx.x;
    int t = threadIdx.x;
    ln_row(in + (size_t)row * E_, g, b, outf ? outf + (size_t)row * E_ : nullptr,
           outb ? outb + (size_t)row * E_ : nullptr, red, t);
}

// ---------------- transposes -----------------------------------------------
__global__ void transpose2b(const float* __restrict__ in, int ldin, long long zin,
                            ushort_t* __restrict__ out, int ldout, long long zout) {
    __shared__ float t[32][33];
    in  += (long long)blockIdx.z * zin;
    out += (long long)blockIdx.z * zout;
    int r0 = blockIdx.y * 32, c0 = blockIdx.x * 32;
    int x = threadIdx.x, y = threadIdx.y;
#pragma unroll
    for (int i = 0; i < 32; i += 8) t[y + i][x] = in[(size_t)(r0 + y + i) * ldin + c0 + x];
    __syncthreads();
#pragma unroll
    for (int i = 0; i < 32; i += 8) out[(size_t)(c0 + y + i) * ldout + r0 + x] = hf1(t[x][y + i]);
}

// dual 768x768 weight transpose (z selects src/dst pair)
__global__ void transpose_pair(const float* __restrict__ in0, const float* __restrict__ in1,
                               ushort_t* __restrict__ out) {
    __shared__ float t[32][33];
    const float* in = blockIdx.z ? in1 : in0;
    ushort_t* o = out + (size_t)blockIdx.z * L_ * E_;
    int r0 = blockIdx.y * 32, c0 = blockIdx.x * 32;
    int x = threadIdx.x, y = threadIdx.y;
#pragma unroll
    for (int i = 0; i < 32; i += 8) t[y + i][x] = in[(size_t)(r0 + y + i) * L_ + c0 + x];
    __syncthreads();
#pragma unroll
    for (int i = 0; i < 32; i += 8) o[(size_t)(c0 + y + i) * E_ + r0 + x] = hf1(t[x][y + i]);
}

// fp16 -> fp16 transpose (ynT)
__global__ void transpose2h(const ushort_t* __restrict__ in, int ldin, long long zin,
                            ushort_t* __restrict__ out, int ldout, long long zout) {
    __shared__ ushort_t t[32][34];
    in  += (long long)blockIdx.z * zin;
    out += (long long)blockIdx.z * zout;
    int r0 = blockIdx.y * 32, c0 = blockIdx.x * 32;
    int x = threadIdx.x, y = threadIdx.y;
#pragma unroll
    for (int i = 0; i < 32; i += 8) t[y + i][x] = in[(size_t)(r0 + y + i) * ldin + c0 + x];
    __syncthreads();
#pragma unroll
    for (int i = 0; i < 32; i += 8) out[(size_t)(c0 + y + i) * ldout + r0 + x] = t[x][y + i];
}

// bias prep + rowsum zero (grid 384 x 256 covers 98304)
__global__ void prep_all(const float* __restrict__ bq, const float* __restrict__ bk,
                         const float* __restrict__ bv) {
    int i = blockIdx.x * 256 + threadIdx.x;
    if (i < B_ * H_ * N_TOK) g_rs[i] = 0.f;
    if (i < E_) {
        g_bqk[i] = bq[i];
        g_bqk[E_ + i] = bk[i];
        float s = 0.f;
#pragma unroll
        for (int h = 0; h < H_; h++) s += bv[h * E_ + i];
        g_bsum[i] = s;
    }
}

#define STG  3
#define AST  8192u    // stage bytes (128 rows * 64 B)

// ---------------- scores kernel: strip-mined exp(q@k^T/8) ------------------
// One CTA per (row-block 128, b*H+h). q tile staged once (2 chunk buffers);
// k tiles stream through a 3-stage cp.async ring over 8 j-tiles (16 chunks).
// Outputs fp16 expA (unnormalized) + fp32 row sums (2 atomics/row).
__global__ __launch_bounds__(256, 2) void scores_kernel(
    const ushort_t* __restrict__ qb, const ushort_t* __restrict__ kb,
    ushort_t* __restrict__ Ab, float* __restrict__ rs)
{
    __shared__ ushort_t Sm[(2 * AST + STG * AST) / 2];   // 40 KB: q 2 stages, k ring 3

    int tid = threadIdx.x;
    int wid = tid >> 5;
    int lane = tid & 31;
    int g = lane >> 2;
    int tig = lane & 3;
    int warp_m = wid & 3;
    int warp_n = wid >> 2;

    int z = blockIdx.y;              // b*H + h
    int zq = z / H_, zr = z % H_;
    int brow = blockIdx.x * 128;

    const ushort_t* Aq = qb + (size_t)zq * N_TOK * L_ + zr * HD_;
    const ushort_t* Bk = kb + (size_t)zq * M_TOK * L_ + zr * HD_;
    ushort_t* Co = Ab + (size_t)z * N_TOK * M_TOK;
    rs += (size_t)z * N_TOK;

    uint32_t asA = (uint32_t)__cvta_generic_to_shared(&Sm[0]);
    uint32_t asB = asA + 2 * AST;

    // staging coords (identical scheme to tgemm)
    int r = tid >> 1;
    int sg0 = (tid & 1) * 2;
    uint32_t swzS = (uint32_t)((r >> 1) & 3);
    uint32_t dA0 = asA + r * 64 + ((sg0 ^ swzS)) * 16;
    uint32_t dA1 = asA + r * 64 + (((sg0 + 1) ^ swzS)) * 16;
    uint32_t dB0 = asB + r * 64 + ((sg0 ^ swzS)) * 16;
    uint32_t dB1 = asB + r * 64 + (((sg0 + 1) ^ swzS)) * 16;
    const ushort_t* Ag = Aq + (size_t)(brow + r) * L_ + sg0 * 8;

    // prologue: q both chunks + k chunk (j=0,c=0) in group 0; k (0,1) in group 1
    asm volatile("cp.async.cg.shared.global [%0], [%1], 16;" :: "r"(dA0), "l"(Ag));
    asm volatile("cp.async.cg.shared.global [%0], [%1], 16;" :: "r"(dA1), "l"(Ag + 8));
    asm volatile("cp.async.cg.shared.global [%0], [%1], 16;" :: "r"(dA0 + AST), "l"(Ag + 32));
    asm volatile("cp.async.cg.shared.global [%0], [%1], 16;" :: "r"(dA1 + AST), "l"(Ag + 40));
#define KISSUE(stg, jj, cc) do { \
        const ushort_t* _b = Bk + (size_t)((jj) * 128 + r) * L_ + (cc) * 32 + sg0 * 8; \
        asm volatile("cp.async.cg.shared.global [%0], [%1], 16;" :: "r"(dB0 + (stg) * AST), "l"(_b)); \
        asm volatile("cp.async.cg.shared.global [%0], [%1], 16;" :: "r"(dB1 + (stg) * AST), "l"(_b + 8)); \
    } while (0)
    KISSUE(0, 0, 0);
    asm volatile("cp.async.commit_group;");
    KISSUE(1, 0, 1);
    asm volatile("cp.async.commit_group;");

    // ldmatrix addressing
    int sub = lane >> 3, r8 = lane & 7;
    uint32_t aBase[2], aSwz[2], bBase[4], bSwz[4];
#pragma unroll
    for (int mi = 0; mi < 2; mi++) {
        int row = warp_m * 32 + mi * 16 + (sub & 1) * 8 + r8;
        aBase[mi] = asA + row * 64;
        aSwz[mi] = (uint32_t)((row >> 1) & 3);
    }
#pragma unroll
    for (int nq = 0; nq < 4; nq++) {
        int row = warp_n * 64 + nq * 16 + (sub >> 1) * 8 + r8;
        bBase[nq] = asB + row * 64;
        bSwz[nq] = (uint32_t)((row >> 1) & 3);
    }
    uint32_t segA = (uint32_t)(sub >> 1);
    uint32_t segB = (uint32_t)(sub & 1);

    float s_lo[2] = {0.f, 0.f}, s_hi[2] = {0.f, 0.f};
    int sB = 0, cidx = 0;

    for (int j = 0; j < 8; j++) {
        float acc[2][8][4];
#pragma unroll
        for (int i = 0; i < 2; i++)
#pragma unroll
            for (int jj = 0; jj < 8; jj++)
#pragma unroll
                for (int c = 0; c < 4; c++) acc[i][jj][c] = 0.f;

#pragma unroll
        for (int c = 0; c < 2; c++) {
            asm volatile("cp.async.wait_group 1;");
            __syncthreads();
            uint32_t sbA = (uint32_t)(c * AST);
            uint32_t sbB = (uint32_t)(sB * AST);

#pragma unroll
            for (int h = 0; h < 2; h++) {
                uint32_t a[2][4], b[4][4];
#pragma unroll
                for (int mi = 0; mi < 2; mi++)
                    LDMX4(a[mi], aBase[mi] + sbA + (((2 * h + segA) ^ aSwz[mi]) << 4));
#pragma unroll
                for (int nq = 0; nq < 4; nq++)
                    LDMX4(b[nq], bBase[nq] + sbB + (((2 * h + segB) ^ bSwz[nq]) << 4));

#pragma unroll
                for (int p = 0; p < 4; p++)
#pragma unroll
                    for (int h2 = 0; h2 < 2; h2++) {
                        int nj = 2 * p + h2;
                        uint32_t b0 = b[p][h2 * 2], b1 = b[p][h2 * 2 + 1];
#pragma unroll
                        for (int mi = 0; mi < 2; mi++)
                            mma_f16(acc[mi][nj][0], acc[mi][nj][1], acc[mi][nj][2], acc[mi][nj][3],
                                    a[mi][0], a[mi][1], a[mi][2], a[mi][3], b0, b1);
                    }
            }

            if (cidx + 2 < 16) {
                int nxt = cidx + 2;
                int stg = sB + 2; if (stg >= STG) stg -= STG;
                KISSUE(stg, nxt >> 1, nxt & 1);
            }
            asm volatile("cp.async.commit_group;");
            if (++sB == STG) sB = 0;
            cidx++;
        }

        // epilogue for j-tile: exp + store + rowsum accumulation
#pragma unroll
        for (int mi = 0; mi < 2; mi++) {
            int r0 = brow + warp_m * 32 + mi * 16 + g;
#pragma unroll
            for (int nj = 0; nj < 8; nj++) {
                int col = j * 128 + warp_n * 64 + nj * 8 + 2 * tig;
                float e0 = exp_fma(acc[mi][nj][0] * 0.125f);
                float e1 = exp_fma(acc[mi][nj][1] * 0.125f);
                float e2 = exp_fma(acc[mi][nj][2] * 0.125f);
                float e3 = exp_fma(acc[mi][nj][3] * 0.125f);
                uint32_t p0 = hf2(e0, e1);
                uint32_t p1 = hf2(e2, e3);
                s_lo[mi] += h2f((ushort_t)(p0 & 0xffff)) + h2f((ushort_t)(p0 >> 16));
                s_hi[mi] += h2f((ushort_t)(p1 & 0xffff)) + h2f((ushort_t)(p1 >> 16));
                *reinterpret_cast<uint32_t*>(Co + (size_t)r0 * M_TOK + col) = p0;
                *reinterpret_cast<uint32_t*>(Co + (size_t)(r0 + 8) * M_TOK + col) = p1;
            }
        }
    }
#undef KISSUE

    // final row-sum atomics (2 warp_n contributors per row)
#pragma unroll
    for (int mi = 0; mi < 2; mi++) {
        float lo = s_lo[mi], hi = s_hi[mi];
        lo += __shfl_xor_sync(0xffffffffu, lo, 1);
        lo += __shfl_xor_sync(0xffffffffu, lo, 2);
        hi += __shfl_xor_sync(0xffffffffu, hi, 1);
        hi += __shfl_xor_sync(0xffffffffu, hi, 2);
        if (tig == 0) {
            int r0 = brow + warp_m * 32 + mi * 16 + g;
            atomicAdd(&rs[r0], lo);
            atomicAdd(&rs[r0 + 8], hi);
        }
    }
}

// ---------------- fp16 GEMM: cp.async 3-stage BK=32 + ldmatrix + mma -------
// D = alpha * Aop @ Bop^T (fp16 K-major). CTA 128x128, 8 warps 4m x 2n.
// OM: 0 = fp32 out (+bias/res), 1 = fp16 out (+bias),
//     3 = fp16 out scaled per-row by 1/rsum[row].
// NOTE: for OM!=0, all C strides/ld are in ushort (fp16 element) units.
template <int OM, bool RELU>
__global__ __launch_bounds__(256, 2) void tgemm(
    int K, int zdiv,
    const ushort_t* __restrict__ A, int lda, long long sA1, long long sA2,
    const ushort_t* __restrict__ Bop, int ldb, long long sB1, long long sB2,
    void* Cop, int ldc, long long sC1, long long sC2,
    const float* __restrict__ bias, long long sBias,
    const float* __restrict__ res, int ldr, long long sR1, long long sR2,
    float* rsum,
    float alpha)
{
    __shared__ ushort_t Sm[(2 * STG * AST) / 2];   // 48 KB

    int tid = threadIdx.x;
    int wid = tid >> 5;
    int lane = tid & 31;
    int g = lane >> 2;
    int tig = lane & 3;
    int warp_m = wid & 3;
    int warp_n = wid >> 2;

    int z = blockIdx.z;
    long long zq = z / zdiv, zr = z % zdiv;
    A   += zq * sA1 + zr * sA2;
    Bop += zq * sB1 + zr * sB2;
    long long coff = zq * sC1 + zr * sC2;
    if (bias) bias += zq * sBias;
    if (res) res += zq * sR1 + zr * sR2;
    if (OM == 3) rsum += (long long)z * N_TOK;

    int brow = blockIdx.y * 128;
    int bcol = blockIdx.x * 128;

    uint32_t asA = (uint32_t)__cvta_generic_to_shared(&Sm[0]);
    uint32_t asB = asA + STG * AST;

    int r = tid >> 1;
    int sg0 = (tid & 1) * 2;
    uint32_t swzS = (uint32_t)((r >> 1) & 3);
    uint32_t dA0 = asA + r * 64 + ((sg0 ^ swzS)) * 16;
    uint32_t dA1 = asA + r * 64 + (((sg0 + 1) ^ swzS)) * 16;
    uint32_t dB0 = dA0 + STG * AST;
    uint32_t dB1 = dA1 + STG * AST;
    const ushort_t* Ag = A + (size_t)(brow + r) * lda + sg0 * 8;
    const ushort_t* Bg = Bop + (size_t)(bcol + r) * ldb + sg0 * 8;

    int nchunk = K >> 5;

#define ISSUE(s, chunk) do { \
        const ushort_t* _a = Ag + (size_t)(chunk) * 32; \
        const ushort_t* _b = Bg + (size_t)(chunk) * 32; \
        asm volatile("cp.async.cg.shared.global [%0], [%1], 16;" :: "r"(dA0 + (s) * AST), "l"(_a)); \
        asm volatile("cp.async.cg.shared.global [%0], [%1], 16;" :: "r"(dA1 + (s) * AST), "l"(_a + 8)); \
        asm volatile("cp.async.cg.shared.global [%0], [%1], 16;" :: "r"(dB0 + (s) * AST), "l"(_b)); \
        asm volatile("cp.async.cg.shared.global [%0], [%1], 16;" :: "r"(dB1 + (s) * AST), "l"(_b + 8)); \
    } while (0)

    ISSUE(0, 0);
    asm volatile("cp.async.commit_group;");
    if (nchunk > 1) ISSUE(1, 1);
    asm volatile("cp.async.commit_group;");

    int sub = lane >> 3, r8 = lane & 7;
    uint32_t aBase[2], aSwz[2], bBase[4], bSwz[4];
#pragma unroll
    for (int mi = 0; mi < 2; mi++) {
        int row = warp_m * 32 + mi * 16 + (sub & 1) * 8 + r8;
        aBase[mi] = asA + row * 64;
        aSwz[mi] = (uint32_t)((row >> 1) & 3);
    }
#pragma unroll
    for (int nq = 0; nq < 4; nq++) {
        int row = warp_n * 64 + nq * 16 + (sub >> 1) * 8 + r8;
        bBase[nq] = asB + row * 64;
        bSwz[nq] = (uint32_t)((row >> 1) & 3);
    }
    uint32_t segA = (uint32_t)(sub >> 1);
    uint32_t segB = (uint32_t)(sub & 1);

    float acc[2][8][4];
#pragma unroll
    for (int i = 0; i < 2; i++)
#pragma unroll
        for (int j = 0; j < 8; j++)
#pragma unroll
            for (int c = 0; c < 4; c++) acc[i][j][c] = 0.f;

    int s = 0;
    for (int i = 0; i < nchunk; i++) {
        asm volatile("cp.async.wait_group 1;");
        __syncthreads();
        uint32_t sb = (uint32_t)(s * AST);

#pragma unroll
        for (int h = 0; h < 2; h++) {
            uint32_t a[2][4], b[4][4];
#pragma unroll
            for (int mi = 0; mi < 2; mi++)
                LDMX4(a[mi], aBase[mi] + sb + (((2 * h + segA) ^ aSwz[mi]) << 4));
#pragma unroll
            for (int nq = 0; nq < 4; nq++)
                LDMX4(b[nq], bBase[nq] + sb + (((2 * h + segB) ^ bSwz[nq]) << 4));

#pragma unroll
            for (int p = 0; p < 4; p++)
#pragma unroll
                for (int h2 = 0; h2 < 2; h2++) {
                    int nj = 2 * p + h2;
                    uint32_t b0 = b[p][h2 * 2], b1 = b[p][h2 * 2 + 1];
#pragma unroll
                    for (int mi = 0; mi < 2; mi++)
                        mma_f16(acc[mi][nj][0], acc[mi][nj][1], acc[mi][nj][2], acc[mi][nj][3],
                                a[mi][0], a[mi][1], a[mi][2], a[mi][3], b0, b1);
                }
        }

        if (i + 2 < nchunk) {
            int sn = s + 2; if (sn >= STG) sn -= STG;
            ISSUE(sn, i + 2);
        }
        asm volatile("cp.async.commit_group;");
        if (++s == STG) s = 0;
    }
#undef ISSUE

    // epilogue
    float*    Cf = (float*)Cop + coff;
    ushort_t* Ch = (ushort_t*)Cop + coff;

#pragma unroll
    for (int mi = 0; mi < 2; mi++) {
        int r0 = brow + warp_m * 32 + mi * 16 + g;
        float inv_lo = 1.f, inv_hi = 1.f;
        if (OM == 3) {
            inv_lo = 1.0f / rsum[r0];
            inv_hi = 1.0f / rsum[r0 + 8];
        }
#pragma unroll
        for (int nj = 0; nj < 8; nj++) {
            int col = bcol + warp_n * 64 + nj * 8 + 2 * tig;
            float2 bl = bias ? *reinterpret_cast<const float2*>(bias + col)
                             : make_float2(0.f, 0.f);
            float v0 = acc[mi][nj][0] * alpha + bl.x;
            float v1 = acc[mi][nj][1] * alpha + bl.y;
            float v2 = acc[mi][nj][2] * alpha + bl.x;
            float v3 = acc[mi][nj][3] * alpha + bl.y;
            if (OM == 3) {
                v0 *= inv_lo; v1 *= inv_lo;
                v2 *= inv_hi; v3 *= inv_hi;
            }
            if (res) {
                float2 r0v = *reinterpret_cast<const float2*>(res + (size_t)r0 * ldr + col);
                float2 r1v = *reinterpret_cast<const float2*>(res + (size_t)(r0 + 8) * ldr + col);
                v0 += r0v.x; v1 += r0v.y; v2 += r1v.x; v3 += r1v.y;
            }
            if (RELU) {
                v0 = fmaxf(v0, 0.f); v1 = fmaxf(v1, 0.f);
                v2 = fmaxf(v2, 0.f); v3 = fmaxf(v3, 0.f);
            }
            if (OM == 0) {
                *reinterpret_cast<float2*>(Cf + (size_t)r0 * ldc + col) = make_float2(v0, v1);
                *reinterpret_cast<float2*>(Cf + (size_t)(r0 + 8) * ldc + col) = make_float2(v2, v3);
            } else {
                *reinterpret_cast<uint32_t*>(Ch + (size_t)r0 * ldc + col) = hf2(v0, v1);
                *reinterpret_cast<uint32_t*>(Ch + (size_t)(r0 + 8) * ldc + col) = hf2(v2, v3);
            }
        }
    }
}

// ---------------- launch ---------------------------------------------------
extern "C" void kernel_launch(void* const* d_in, const int* in_sizes, int n_in,
                              void* d_out, int out_size) {
    const float* x     = (const float*)d_in[0];
    const float* y     = (const float*)d_in[1];
    const float* ln1_g = (const float*)d_in[2];
    const float* ln1_b = (const float*)d_in[3];
    const float* ln2_g = (const float*)d_in[4];
    const float* ln2_b = (const float*)d_in[5];
    const float* ln3_g = (const float*)d_in[6];
    const float* ln3_b = (const float*)d_in[7];
    const float* wq    = (const float*)d_in[8];
    const float* bq    = (const float*)d_in[9];
    const float* wk    = (const float*)d_in[10];
    const float* bk    = (const float*)d_in[11];
    const float* wv    = (const float*)d_in[12];
    const float* bv    = (const float*)d_in[13];
    const float* w_in  = (const float*)d_in[14];
    const float* b_in  = (const float*)d_in[15];
    const float* w_out = (const float*)d_in[16];
    const float* b_out = (const float*)d_in[17];
    float* out = (float*)d_out;

    float *p_xn, *p_hn, *p_hpre, *p_rs, *p_bqk, *p_bsum;
    uint32_t *p_Ab, *p_xyb, *p_hnb, *p_qkb, *p_Cb, *p_ynT;
    uint32_t *p_wqkT, *p_wioT, *p_w2T;
    cudaGetSymbolAddress((void**)&p_xn,   g_xn);
    cudaGetSymbolAddress((void**)&p_hn,   g_hn);
    cudaGetSymbolAddress((void**)&p_hpre, g_hpre);
    cudaGetSymbolAddress((void**)&p_Ab,   g_Ab);
    cudaGetSymbolAddress((void**)&p_xyb,  g_xyb);
    cudaGetSymbolAddress((void**)&p_hnb,  g_hnb);
    cudaGetSymbolAddress((void**)&p_qkb,  g_qkb);
    cudaGetSymbolAddress((void**)&p_Cb,   g_Cb);
    cudaGetSymbolAddress((void**)&p_ynT,  g_ynT);
    cudaGetSymbolAddress((void**)&p_wqkT, g_wqkT);
    cudaGetSymbolAddress((void**)&p_wioT, g_wioT);
    cudaGetSymbolAddress((void**)&p_w2T,  g_w2T);
    cudaGetSymbolAddress((void**)&p_rs,   g_rs);
    cudaGetSymbolAddress((void**)&p_bqk,  g_bqk);
    cudaGetSymbolAddress((void**)&p_bsum, g_bsum);

    const int ROWS = B_ * N_TOK;               // 8192
    const size_t CH = (size_t)B_ * N_TOK * E_; // 6291456
    float* out2 = ((size_t)out_size >= 2 * CH) ? out + CH : nullptr;

    ushort_t* xnb = (ushort_t*)p_xyb;
    ushort_t* ynb = xnb + (size_t)ROWS * E_;
    ushort_t* qb  = (ushort_t*)p_qkb;
    ushort_t* kb  = qb + (size_t)ROWS * L_;
    ushort_t* winT  = (ushort_t*)p_wioT;
    ushort_t* woutT = winT + (size_t)L_ * E_;
    uint32_t* p_mid = p_qkb;                // reuse q half after scores consumed

    dim3 tb(32, 8);

    // #1 LN1 + LN2 merged
    ln_qk<<<2 * ROWS, 256>>>(x, y, ln1_g, ln1_b, ln2_g, ln2_b,
                             p_xn, xnb, out2, ynb);

    // #2 wq|wk transpose; #3 bias + rowsum-zero prep; #4 ynT transpose
    transpose_pair<<<dim3(24, 24, 2), tb>>>(wq, wk, (ushort_t*)p_wqkT);
    prep_all<<<384, 256>>>(bq, bk, bv);
    transpose2h<<<dim3(24, 32, B_), tb>>>(ynb, E_, (long long)M_TOK * E_,
                                           (ushort_t*)p_ynT, M_TOK, (long long)E_ * M_TOK);

    // #5 q|k projection, batched z=2
    tgemm<1, false><<<dim3(6, 64, 2), 256>>>(
        E_, 1,
        xnb, E_, (long long)ROWS * E_, 0,
        (ushort_t*)p_wqkT, E_, (long long)L_ * E_, 0,
        p_qkb, L_, (long long)ROWS * L_, 0,
        p_bqk, L_, nullptr, 0, 0, 0, nullptr, 1.0f);

    // #6 scores: strip-mined exp(q@k^T/8) -> fp16 expA + rowsums
    scores_kernel<<<dim3(8, B_ * H_), 256>>>(qb, kb, (ushort_t*)p_Ab, p_rs);

    // remaining prep
    transpose2b<<<dim3(24, 24, H_), tb>>>(wv, H_ * E_, E_, (ushort_t*)p_w2T, H_ * E_, E_);
    transpose_pair<<<dim3(24, 24, 2), tb>>>(w_in, w_out, (ushort_t*)p_wioT);

    // C = softmax(A)_h @ yn : fp16, per-row 1/rowsum scale -> fp16
    tgemm<3, false><<<dim3(6, 8, B_ * H_), 256>>>(
        M_TOK, H_,
        (ushort_t*)p_Ab, M_TOK, (long long)H_ * N_TOK * M_TOK, (long long)N_TOK * M_TOK,
        (ushort_t*)p_ynT, M_TOK, (long long)E_ * M_TOK, 0,
        p_Cb, H_ * E_, (long long)N_TOK * H_ * E_, E_,
        nullptr, 0, nullptr, 0, 0, 0, p_rs, 1.0f);

    // h_pre = xn + C @ W2 + bsum : fp16 -> fp32
    tgemm<0, false><<<dim3(6, 64, 1), 256>>>(
        H_ * E_, 1,
        (ushort_t*)p_Cb, H_ * E_, 0, 0,
        (ushort_t*)p_w2T, H_ * E_, 0, 0,
        p_hpre, E_, 0, 0,
        p_bsum, 0, p_xn, E_, 0, 0, nullptr, 1.0f);

    // LN3 -> fp32 + fp16
    ln_kernel<<<ROWS, 256>>>(p_hpre, ln3_g, ln3_b, p_hn, (ushort_t*)p_hnb);

    // mid = relu(hn @ w_in + b_in) -> fp16
    tgemm<1, true><<<dim3(6, 64, 1), 256>>>(
        E_, 1,
        (ushort_t*)p_hnb, E_, 0, 0,
        winT, E_, 0, 0,
        p_mid, L_, 0, 0,
        b_in, 0, nullptr, 0, 0, 0, nullptr, 1.0f);

    // out = hn + mid @ w_out + b_out -> fp32 into d_out
    tgemm<0, false><<<dim3(6, 64, 1), 256>>>(
        L_, 1,
        (ushort_t*)p_mid, L_, 0, 0,
        woutT, L_, 0, 0,
        out, E_, 0, 0,
        b_out, 0, p_hn, E_, 0, 0, nullptr, 1.0f);
}